// round 1
// baseline (speedup 1.0000x reference)
#include <cuda_runtime.h>
#include <math.h>

#define B_   2
#define S_   2048
#define D_   512
#define H_   8
#define HD_  64
#define MTOK (B_*S_)      // 4096
#define DFF  (4*D_)       // 2048

// ---------------- scratch (device globals; no allocation allowed) ----------
__device__ float g_nx [MTOK*D_];
__device__ float g_q  [MTOK*D_];
__device__ float g_k  [MTOK*D_];
__device__ float g_v  [MTOK*D_];
__device__ float g_att[MTOK*D_];
__device__ float g_x1 [MTOK*D_];
__device__ float g_n2 [MTOK*D_];
__device__ float g_h  [MTOK*DFF];

// ---------------- LayerNorm: one block per row (512 elems) -----------------
__global__ __launch_bounds__(256) void ln_kernel(
    const float* __restrict__ x, const float* __restrict__ g,
    const float* __restrict__ b, float* __restrict__ out)
{
    int row = blockIdx.x;
    const float2 v = ((const float2*)(x + (long long)row*D_))[threadIdx.x];
    float s  = v.x + v.y;
    float ss = v.x*v.x + v.y*v.y;
    #pragma unroll
    for (int o = 16; o; o >>= 1) {
        s  += __shfl_xor_sync(0xffffffffu, s,  o);
        ss += __shfl_xor_sync(0xffffffffu, ss, o);
    }
    __shared__ float sm_s[8], sm_ss[8];
    int w = threadIdx.x >> 5, l = threadIdx.x & 31;
    if (l == 0) { sm_s[w] = s; sm_ss[w] = ss; }
    __syncthreads();
    float ts = 0.f, tss = 0.f;
    #pragma unroll
    for (int i = 0; i < 8; i++) { ts += sm_s[i]; tss += sm_ss[i]; }
    float mu  = ts * (1.0f/D_);
    float var = tss * (1.0f/D_) - mu*mu;
    float inv = rsqrtf(var + 1e-5f);
    float2 gg = ((const float2*)g)[threadIdx.x];
    float2 bb = ((const float2*)b)[threadIdx.x];
    float2 o;
    o.x = (v.x - mu)*inv*gg.x + bb.x;
    o.y = (v.y - mu)*inv*gg.y + bb.y;
    ((float2*)(out + (long long)row*D_))[threadIdx.x] = o;
}

// ---------------- SGEMM 128x128x16, 256 thr, 8x8 micro ---------------------
// C[M,N] = A[M,K] @ B[K,N] + bias[N]  (+ epilogue variant)
#define EPI_PLAIN 0
#define EPI_QKV   1   // scatter into [B,H,S,HD]
#define EPI_RESID 2   // += resid[r*N+c]
#define EPI_GELU  3   // exact gelu

template<int EPI>
__global__ __launch_bounds__(256) void gemm_kernel(
    const float* __restrict__ A, const float* __restrict__ Bm,
    const float* __restrict__ bias, const float* __restrict__ resid,
    float* __restrict__ C, int M, int N, int K)
{
    const int AST = 132;                       // padded stride for As (16B aligned)
    __shared__ float As[16*AST];
    __shared__ float Bs[16*128];
    const int t  = threadIdx.x;
    const int m0 = blockIdx.y * 128, n0 = blockIdx.x * 128;
    const int ty = t >> 4, tx = t & 15;

    float acc[8][8];
    #pragma unroll
    for (int i = 0; i < 8; i++)
        #pragma unroll
        for (int j = 0; j < 8; j++) acc[i][j] = 0.f;

    for (int k0 = 0; k0 < K; k0 += 16) {
        // A tile 128x16, stored transposed As[k][m]
        #pragma unroll
        for (int i = 0; i < 2; i++) {
            int li  = t + i*256;               // [0,512)
            int row = li >> 2, c4 = li & 3;
            float4 va = *(const float4*)(A + (long long)(m0+row)*K + k0 + c4*4);
            As[(c4*4+0)*AST + row] = va.x;
            As[(c4*4+1)*AST + row] = va.y;
            As[(c4*4+2)*AST + row] = va.z;
            As[(c4*4+3)*AST + row] = va.w;
        }
        // B tile 16x128, natural
        #pragma unroll
        for (int i = 0; i < 2; i++) {
            int li  = t + i*256;
            int row = li >> 5, c4 = li & 31;
            *(float4*)(Bs + row*128 + c4*4) =
                *(const float4*)(Bm + (long long)(k0+row)*N + n0 + c4*4);
        }
        __syncthreads();
        #pragma unroll
        for (int kk = 0; kk < 16; kk++) {
            float4 a0 = *(float4*)(As + kk*AST + ty*8);
            float4 a1 = *(float4*)(As + kk*AST + ty*8 + 4);
            float4 b0 = *(float4*)(Bs + kk*128 + tx*8);
            float4 b1 = *(float4*)(Bs + kk*128 + tx*8 + 4);
            float av[8] = {a0.x,a0.y,a0.z,a0.w,a1.x,a1.y,a1.z,a1.w};
            float bv[8] = {b0.x,b0.y,b0.z,b0.w,b1.x,b1.y,b1.z,b1.w};
            #pragma unroll
            for (int i = 0; i < 8; i++)
                #pragma unroll
                for (int j = 0; j < 8; j++)
                    acc[i][j] += av[i]*bv[j];
        }
        __syncthreads();
    }

    #pragma unroll
    for (int i = 0; i < 8; i++) {
        int r = m0 + ty*8 + i;
        #pragma unroll
        for (int j = 0; j < 8; j++) {
            int c = n0 + tx*8 + j;
            float v = acc[i][j] + bias[c];
            if (EPI == EPI_RESID) v += resid[(long long)r*N + c];
            if (EPI == EPI_GELU)  v = 0.5f*v*(1.0f + erff(v*0.70710678118654752f));
            if (EPI == EPI_QKV) {
                int bb = r >> 11, s = r & (S_-1);   // S_=2048
                int h  = c >> 6,  hd = c & 63;      // HD_=64
                C[(((long long)(bb*H_ + h))*S_ + s)*HD_ + hd] = v;
            } else {
                C[(long long)r*N + c] = v;
            }
        }
    }
}

// ---------------- flash attention, 64-row Q tiles, 64 key tiles ------------
#define SPAD 68
__global__ __launch_bounds__(256) void attn_kernel(
    const float* __restrict__ Q, const float* __restrict__ Km,
    const float* __restrict__ V,
    const int*   __restrict__ adj, const float* __restrict__ edge,
    float* __restrict__ Out)
{
    extern __shared__ float smx[];
    float* Qs = smx;                 // [hd][q]   64 x SPAD
    float* Ks = smx + 64*SPAD;       // [hd][key]
    float* Vs = smx + 2*64*SPAD;     // [key][hd]
    float* Ps = smx + 3*64*SPAD;     // [key][q]

    const int t  = threadIdx.x;
    const int q0 = blockIdx.x * 64;
    const int h  = blockIdx.y;
    const int bb = blockIdx.z;
    const int ty = t >> 4, tx = t & 15;
    const long long bhs = (long long)(bb*H_ + h)*S_;

    // load Q tile transposed -> Qs[hd][q]
    const float* Qb = Q + (bhs + q0)*HD_;
    #pragma unroll
    for (int i = 0; i < 4; i++) {
        int idx = t + i*256;               // [0,1024)
        int row = idx >> 4, c4 = idx & 15;
        float4 v = *(const float4*)(Qb + row*HD_ + c4*4);
        Qs[(c4*4+0)*SPAD + row] = v.x;
        Qs[(c4*4+1)*SPAD + row] = v.y;
        Qs[(c4*4+2)*SPAD + row] = v.z;
        Qs[(c4*4+3)*SPAD + row] = v.w;
    }

    float m[4], l[4], acc[4][4];
    #pragma unroll
    for (int i = 0; i < 4; i++) {
        m[i] = -1e30f; l[i] = 0.f;
        #pragma unroll
        for (int j = 0; j < 4; j++) acc[i][j] = 0.f;
    }

    for (int kt = 0; kt < S_; kt += 64) {
        const float* Kb = Km + (bhs + kt)*HD_;
        const float* Vb = V  + (bhs + kt)*HD_;
        #pragma unroll
        for (int i = 0; i < 4; i++) {
            int idx = t + i*256;
            int row = idx >> 4, c4 = idx & 15;
            float4 v = *(const float4*)(Kb + row*HD_ + c4*4);
            Ks[(c4*4+0)*SPAD + row] = v.x;
            Ks[(c4*4+1)*SPAD + row] = v.y;
            Ks[(c4*4+2)*SPAD + row] = v.z;
            Ks[(c4*4+3)*SPAD + row] = v.w;
            float4 w = *(const float4*)(Vb + row*HD_ + c4*4);
            *(float4*)(Vs + row*SPAD + c4*4) = w;
        }
        __syncthreads();

        // S = Q @ K^T
        float s[4][4];
        #pragma unroll
        for (int i = 0; i < 4; i++)
            #pragma unroll
            for (int j = 0; j < 4; j++) s[i][j] = 0.f;
        #pragma unroll
        for (int kk = 0; kk < 64; kk++) {
            float4 a = *(float4*)(Qs + kk*SPAD + ty*4);
            float4 b = *(float4*)(Ks + kk*SPAD + tx*4);
            float av[4] = {a.x,a.y,a.z,a.w};
            float bv[4] = {b.x,b.y,b.z,b.w};
            #pragma unroll
            for (int i = 0; i < 4; i++)
                #pragma unroll
                for (int j = 0; j < 4; j++)
                    s[i][j] += av[i]*bv[j];
        }

        // scale + mask/bias  (finite -1e30 avoids inf-inf NaN; diag guarantees l>0)
        #pragma unroll
        for (int i = 0; i < 4; i++) {
            int qg = q0 + ty*4 + i;
            const int*   arow = adj  + ((long long)bb*S_ + qg)*S_ + kt + tx*4;
            const float* erow = edge + ((long long)bb*S_ + qg)*S_ + kt + tx*4;
            #pragma unroll
            for (int j = 0; j < 4; j++) {
                int a_ = arow[j];
                s[i][j] = (a_ > 0) ? (s[i][j]*0.125f + 0.1f*erow[j]*(float)a_)
                                   : -1e30f;
            }
        }

        // online softmax
        #pragma unroll
        for (int i = 0; i < 4; i++) {
            float rm = fmaxf(fmaxf(s[i][0], s[i][1]), fmaxf(s[i][2], s[i][3]));
            #pragma unroll
            for (int o = 1; o < 16; o <<= 1)
                rm = fmaxf(rm, __shfl_xor_sync(0xffffffffu, rm, o));
            float mn = fmaxf(m[i], rm);
            float al = __expf(m[i] - mn);
            m[i] = mn;
            float rs = 0.f;
            #pragma unroll
            for (int j = 0; j < 4; j++) {
                float p = __expf(s[i][j] - mn);
                s[i][j] = p; rs += p;
            }
            #pragma unroll
            for (int o = 1; o < 16; o <<= 1)
                rs += __shfl_xor_sync(0xffffffffu, rs, o);
            l[i] = l[i]*al + rs;
            #pragma unroll
            for (int j = 0; j < 4; j++) acc[i][j] *= al;
        }

        // P -> smem transposed [key][q]
        #pragma unroll
        for (int i = 0; i < 4; i++)
            #pragma unroll
            for (int j = 0; j < 4; j++)
                Ps[(tx*4+j)*SPAD + ty*4 + i] = s[i][j];
        __syncthreads();

        // O += P @ V
        #pragma unroll
        for (int kk = 0; kk < 64; kk++) {
            float4 a = *(float4*)(Ps + kk*SPAD + ty*4);
            float4 b = *(float4*)(Vs + kk*SPAD + tx*4);
            float av[4] = {a.x,a.y,a.z,a.w};
            float bv[4] = {b.x,b.y,b.z,b.w};
            #pragma unroll
            for (int i = 0; i < 4; i++)
                #pragma unroll
                for (int j = 0; j < 4; j++)
                    acc[i][j] += av[i]*bv[j];
        }
        __syncthreads();
    }

    // write out in [B,S,D] layout so O-projection is a plain GEMM
    #pragma unroll
    for (int i = 0; i < 4; i++) {
        int qg = q0 + ty*4 + i;
        float inv = 1.0f / l[i];
        #pragma unroll
        for (int j = 0; j < 4; j++)
            Out[((long long)bb*S_ + qg)*D_ + h*HD_ + tx*4 + j] = acc[i][j]*inv;
    }
}

// ---------------------------- launch ---------------------------------------
extern "C" void kernel_launch(void* const* d_in, const int* in_sizes, int n_in,
                              void* d_out, int out_size)
{
    const float* x    = (const float*)d_in[0];
    const int*   adj  = (const int*)  d_in[1];
    const float* edge = (const float*)d_in[2];
    const float* ln1g = (const float*)d_in[3];
    const float* ln1b = (const float*)d_in[4];
    const float* ln2g = (const float*)d_in[5];
    const float* ln2b = (const float*)d_in[6];
    const float* wq = (const float*)d_in[7];  const float* bq = (const float*)d_in[8];
    const float* wk = (const float*)d_in[9];  const float* bk = (const float*)d_in[10];
    const float* wv = (const float*)d_in[11]; const float* bv = (const float*)d_in[12];
    const float* wo = (const float*)d_in[13]; const float* bo = (const float*)d_in[14];
    const float* w1 = (const float*)d_in[15]; const float* b1 = (const float*)d_in[16];
    const float* w2 = (const float*)d_in[17]; const float* b2 = (const float*)d_in[18];
    float* out = (float*)d_out;

    float *nx, *q, *k, *v, *att, *x1, *n2, *hbuf;
    cudaGetSymbolAddress((void**)&nx,   g_nx);
    cudaGetSymbolAddress((void**)&q,    g_q);
    cudaGetSymbolAddress((void**)&k,    g_k);
    cudaGetSymbolAddress((void**)&v,    g_v);
    cudaGetSymbolAddress((void**)&att,  g_att);
    cudaGetSymbolAddress((void**)&x1,   g_x1);
    cudaGetSymbolAddress((void**)&n2,   g_n2);
    cudaGetSymbolAddress((void**)&hbuf, g_h);

    const int attn_smem = 4*64*SPAD*(int)sizeof(float);   // 69632 B
    cudaFuncSetAttribute(attn_kernel,
                         cudaFuncAttributeMaxDynamicSharedMemorySize, attn_smem);

    // 1) LN1
    ln_kernel<<<MTOK, 256>>>(x, ln1g, ln1b, nx);

    // 2) Q/K/V projections -> [B,H,S,HD]
    dim3 g1(D_/128, MTOK/128);                // (4, 32)
    gemm_kernel<EPI_QKV><<<g1, 256>>>(nx, wq, bq, nullptr, q,  MTOK, D_, D_);
    gemm_kernel<EPI_QKV><<<g1, 256>>>(nx, wk, bk, nullptr, k,  MTOK, D_, D_);
    gemm_kernel<EPI_QKV><<<g1, 256>>>(nx, wv, bv, nullptr, v,  MTOK, D_, D_);

    // 3) masked flash attention -> [B,S,D]
    dim3 ga(S_/64, H_, B_);                   // (32, 8, 2)
    attn_kernel<<<ga, 256, attn_smem>>>(q, k, v, adj, edge, att);

    // 4) O projection + residual
    gemm_kernel<EPI_RESID><<<g1, 256>>>(att, wo, bo, x, x1, MTOK, D_, D_);

    // 5) LN2
    ln_kernel<<<MTOK, 256>>>(x1, ln2g, ln2b, n2);

    // 6) MLP up + exact GELU
    dim3 g2(DFF/128, MTOK/128);               // (16, 32)
    gemm_kernel<EPI_GELU><<<g2, 256>>>(n2, w1, b1, nullptr, hbuf, MTOK, DFF, D_);

    // 7) MLP down + residual -> final output
    gemm_kernel<EPI_RESID><<<g1, 256>>>(hbuf, w2, b2, x1, out, MTOK, D_, DFF);
}

// round 3
// speedup vs baseline: 3.5189x; 3.5189x over previous
#include <cuda_runtime.h>
#include <cuda_bf16.h>
#include <math.h>
#include <cstdint>

#define B_   2
#define S_   2048
#define D_   512
#define H_   8
#define HD_  64
#define MTOK (B_*S_)      // 4096
#define DFF  (4*D_)       // 2048

// ---------------- scratch (device globals; no allocation allowed) ----------
__device__ float g_x1  [MTOK*D_];
__device__ float g_bias[(long long)B_*S_*S_];          // combined mask+edge bias

// bf16 split activation buffers
__device__ __nv_bfloat16 g_pa_hi[MTOK*D_];             // nx / att / n2
__device__ __nv_bfloat16 g_pa_lo[MTOK*D_];
__device__ __nv_bfloat16 g_qa_hi[MTOK*DFF];            // mlp hidden
__device__ __nv_bfloat16 g_qa_lo[MTOK*DFF];

// q/k/v bf16 split [B,H,S,HD]
__device__ __nv_bfloat16 g_qh[MTOK*D_], g_ql[MTOK*D_];
__device__ __nv_bfloat16 g_kh[MTOK*D_], g_kl[MTOK*D_];
__device__ __nv_bfloat16 g_vh[MTOK*D_], g_vl[MTOK*D_];

// bf16 split transposed weights [N][K]
__device__ __nv_bfloat16 g_wqkv_hi[3*D_*D_], g_wqkv_lo[3*D_*D_];
__device__ __nv_bfloat16 g_wo_hi[D_*D_],    g_wo_lo[D_*D_];
__device__ __nv_bfloat16 g_w1_hi[DFF*D_],   g_w1_lo[DFF*D_];
__device__ __nv_bfloat16 g_w2_hi[D_*DFF],   g_w2_lo[D_*DFF];

// ======================= PTX helpers ========================================
__device__ __forceinline__ uint32_t smem_u32(const void* p) {
    uint32_t a;
    asm("{ .reg .u64 t; cvta.to.shared.u64 t, %1; cvt.u32.u64 %0, t; }"
        : "=r"(a) : "l"(p));
    return a;
}
#define CP_ASYNC16(dst, src) \
    asm volatile("cp.async.cg.shared.global [%0], [%1], 16;" :: "r"(dst), "l"(src))
#define CP_COMMIT() asm volatile("cp.async.commit_group;" ::: "memory")
#define CP_WAIT(n)  asm volatile("cp.async.wait_group %0;" :: "n"(n) : "memory")

__device__ __forceinline__ void ldsm_x4(uint32_t* r, uint32_t a) {
    asm volatile("ldmatrix.sync.aligned.m8n8.x4.shared.b16 {%0,%1,%2,%3}, [%4];"
        : "=r"(r[0]), "=r"(r[1]), "=r"(r[2]), "=r"(r[3]) : "r"(a));
}
__device__ __forceinline__ void ldsm_x4_t(uint32_t* r, uint32_t a) {
    asm volatile("ldmatrix.sync.aligned.m8n8.x4.trans.shared.b16 {%0,%1,%2,%3}, [%4];"
        : "=r"(r[0]), "=r"(r[1]), "=r"(r[2]), "=r"(r[3]) : "r"(a));
}
__device__ __forceinline__ void mma16816(float* c, const uint32_t* a, const uint32_t* b) {
    asm volatile("mma.sync.aligned.m16n8k16.row.col.f32.bf16.bf16.f32 "
        "{%0,%1,%2,%3}, {%4,%5,%6,%7}, {%8,%9}, {%0,%1,%2,%3};"
        : "+f"(c[0]), "+f"(c[1]), "+f"(c[2]), "+f"(c[3])
        : "r"(a[0]), "r"(a[1]), "r"(a[2]), "r"(a[3]), "r"(b[0]), "r"(b[1]));
}
__device__ __forceinline__ uint32_t packbf(float a, float b) {
    __nv_bfloat162 t;
    t.x = __float2bfloat16(a); t.y = __float2bfloat16(b);
    return *(uint32_t*)&t;
}
__device__ __forceinline__ void split_pair(float a, float b, uint32_t& hi, uint32_t& lo) {
    __nv_bfloat16 ha = __float2bfloat16(a), hb = __float2bfloat16(b);
    hi = ((uint32_t)*(uint16_t*)&ha) | ((uint32_t)*(uint16_t*)&hb << 16);
    lo = packbf(a - __bfloat162float(ha), b - __bfloat162float(hb));
}

// ---------------- bias precompute: adj/edge -> combined fp32 ----------------
__global__ __launch_bounds__(256) void bias_kernel(
    const int4* __restrict__ adj, const float4* __restrict__ edge,
    float4* __restrict__ out)
{
    int i = blockIdx.x*256 + threadIdx.x;
    int4 a = adj[i]; float4 e = edge[i]; float4 o;
    o.x = a.x ? 0.1f*e.x : -1e30f;
    o.y = a.y ? 0.1f*e.y : -1e30f;
    o.z = a.z ? 0.1f*e.z : -1e30f;
    o.w = a.w ? 0.1f*e.w : -1e30f;
    out[i] = o;
}

// ---------------- LayerNorm -> bf16 hi/lo split -----------------------------
__global__ __launch_bounds__(256) void ln_bf16_kernel(
    const float* __restrict__ x, const float* __restrict__ g,
    const float* __restrict__ b, __nv_bfloat16* __restrict__ ohi,
    __nv_bfloat16* __restrict__ olo)
{
    int row = blockIdx.x;
    const float2 v = ((const float2*)(x + (long long)row*D_))[threadIdx.x];
    float s  = v.x + v.y;
    float ss = v.x*v.x + v.y*v.y;
    #pragma unroll
    for (int o = 16; o; o >>= 1) {
        s  += __shfl_xor_sync(0xffffffffu, s,  o);
        ss += __shfl_xor_sync(0xffffffffu, ss, o);
    }
    __shared__ float sm_s[8], sm_ss[8];
    int w = threadIdx.x >> 5, l = threadIdx.x & 31;
    if (l == 0) { sm_s[w] = s; sm_ss[w] = ss; }
    __syncthreads();
    float ts = 0.f, tss = 0.f;
    #pragma unroll
    for (int i = 0; i < 8; i++) { ts += sm_s[i]; tss += sm_ss[i]; }
    float mu  = ts * (1.0f/D_);
    float var = tss * (1.0f/D_) - mu*mu;
    float inv = rsqrtf(var + 1e-5f);
    float2 gg = ((const float2*)g)[threadIdx.x];
    float2 bb = ((const float2*)b)[threadIdx.x];
    float ox = (v.x - mu)*inv*gg.x + bb.x;
    float oy = (v.y - mu)*inv*gg.y + bb.y;
    uint32_t hi, lo;
    split_pair(ox, oy, hi, lo);
    *(uint32_t*)(ohi + (long long)row*D_ + threadIdx.x*2) = hi;
    *(uint32_t*)(olo + (long long)row*D_ + threadIdx.x*2) = lo;
}

// ---------------- weight transpose + split: W[K,N] -> T[N,K] hi/lo ----------
__global__ __launch_bounds__(256) void wconvT_kernel(
    const float* __restrict__ W, __nv_bfloat16* __restrict__ Thi,
    __nv_bfloat16* __restrict__ Tlo, int K, int N)
{
    __shared__ float t[32][33];
    int tx = threadIdx.x & 31, ty = threadIdx.x >> 5;
    int k0 = blockIdx.y*32, n0 = blockIdx.x*32;
    #pragma unroll
    for (int i = 0; i < 4; i++)
        t[ty + i*8][tx] = W[(long long)(k0 + ty + i*8)*N + n0 + tx];
    __syncthreads();
    #pragma unroll
    for (int i = 0; i < 4; i++) {
        int n = n0 + ty + i*8, k = k0 + tx;
        float v = t[tx][ty + i*8];
        __nv_bfloat16 h = __float2bfloat16(v);
        Thi[(long long)n*K + k] = h;
        Tlo[(long long)n*K + k] = __float2bfloat16(v - __bfloat162float(h));
    }
}

// ================= HMMA bf16-split GEMM: 128x128 blocks =====================
// C = A[M,K] @ B[N,K]^T ; A,B bf16 hi/lo; 3-product split; fp32 accum.
#define EPI_QKV   1
#define EPI_RESID 2
#define EPI_GELU  3
#define GEMM_SMEM 131072   // 2 stages x (4 tiles x 16KB)

template<int EPI>
__global__ __launch_bounds__(256) void mma_gemm(
    const __nv_bfloat16* __restrict__ Ah, const __nv_bfloat16* __restrict__ Al,
    const __nv_bfloat16* __restrict__ Bh, const __nv_bfloat16* __restrict__ Bl,
    const float* __restrict__ bias0, const float* __restrict__ bias1,
    const float* __restrict__ bias2, const float* __restrict__ resid,
    float* __restrict__ Cf,
    __nv_bfloat16* __restrict__ Oh, __nv_bfloat16* __restrict__ Ol,
    __nv_bfloat16* __restrict__ qh_, __nv_bfloat16* __restrict__ ql_,
    __nv_bfloat16* __restrict__ kh_, __nv_bfloat16* __restrict__ kl_,
    __nv_bfloat16* __restrict__ vh_, __nv_bfloat16* __restrict__ vl_,
    int M, int N, int K)
{
    extern __shared__ char smc[];
    const uint32_t sb = smem_u32(smc);
    const int t = threadIdx.x, lane = t & 31;
    const int wid = t >> 5, wm = wid & 3, wn = wid >> 2;
    const int m0 = blockIdx.y*128, n0 = blockIdx.x*128;

    float acc[2][8][4];
    #pragma unroll
    for (int f = 0; f < 2; f++)
        #pragma unroll
        for (int nf = 0; nf < 8; nf++)
            #pragma unroll
            for (int j = 0; j < 4; j++) acc[f][nf][j] = 0.f;

    auto ld_stage = [&](int st, int k0) {
        #pragma unroll
        for (int i = 0; i < 16; i++) {
            int gid = t + i*256;
            int tile = gid >> 10, idx = gid & 1023;
            int row = idx >> 3, c = idx & 7;
            const __nv_bfloat16* sp = (tile == 0) ? Ah : (tile == 1) ? Al
                                     : (tile == 2) ? Bh : Bl;
            long long grow = (long long)((tile < 2) ? m0 : n0) + row;
            const __nv_bfloat16* src = sp + grow*K + k0 + c*8;
            uint32_t dst = sb + st*65536 + tile*16384 + row*128 + ((c ^ (row & 7)) << 4);
            CP_ASYNC16(dst, src);
        }
    };

    const int NS = K >> 6;
    ld_stage(0, 0);
    CP_COMMIT();
    for (int s = 0; s < NS; s++) {
        if (s + 1 < NS) { ld_stage((s + 1) & 1, (s + 1) << 6); CP_COMMIT(); CP_WAIT(1); }
        else            { CP_WAIT(0); }
        __syncthreads();
        uint32_t base = sb + (s & 1)*65536;
        #pragma unroll
        for (int ks = 0; ks < 4; ks++) {
            uint32_t ah[2][4], al[2][4];
            #pragma unroll
            for (int f = 0; f < 2; f++) {
                int row = wm*32 + f*16 + (lane & 15);
                int ch  = ks*2 + (lane >> 4);
                uint32_t off = row*128 + ((ch ^ (row & 7)) << 4);
                ldsm_x4(ah[f], base + off);
                ldsm_x4(al[f], base + 16384 + off);
            }
            uint32_t bh[4][4], bl[4][4];
            #pragma unroll
            for (int g = 0; g < 4; g++) {
                int row = wn*64 + g*16 + (lane & 7) + ((lane & 16) >> 1);
                int ch  = ks*2 + ((lane >> 3) & 1);
                uint32_t off = row*128 + ((ch ^ (row & 7)) << 4);
                ldsm_x4(bh[g], base + 32768 + off);
                ldsm_x4(bl[g], base + 49152 + off);
            }
            #pragma unroll
            for (int f = 0; f < 2; f++)
                #pragma unroll
                for (int g = 0; g < 4; g++) {
                    mma16816(acc[f][2*g],   ah[f], &bh[g][0]);
                    mma16816(acc[f][2*g+1], ah[f], &bh[g][2]);
                    mma16816(acc[f][2*g],   ah[f], &bl[g][0]);
                    mma16816(acc[f][2*g+1], ah[f], &bl[g][2]);
                    mma16816(acc[f][2*g],   al[f], &bh[g][0]);
                    mma16816(acc[f][2*g+1], al[f], &bh[g][2]);
                }
        }
        __syncthreads();
    }

    // epilogue
    const int lr = lane >> 2, lc = (lane & 3)*2;
    #pragma unroll
    for (int f = 0; f < 2; f++) {
        int r0 = m0 + wm*32 + f*16 + lr;
        #pragma unroll
        for (int nf = 0; nf < 8; nf++) {
            int col = n0 + wn*64 + nf*8 + lc;
            float c0 = acc[f][nf][0], c1 = acc[f][nf][1];
            float c2 = acc[f][nf][2], c3 = acc[f][nf][3];
            if (EPI == EPI_QKV) {
                int which = col >> 9, cq = col & 511;
                const float* bp = (which == 0) ? bias0 : (which == 1) ? bias1 : bias2;
                float2 bv = *(const float2*)(bp + cq);
                c0 += bv.x; c1 += bv.y; c2 += bv.x; c3 += bv.y;
                __nv_bfloat16* dh = (which == 0) ? qh_ : (which == 1) ? kh_ : vh_;
                __nv_bfloat16* dl = (which == 0) ? ql_ : (which == 1) ? kl_ : vl_;
                int hh = cq >> 6, hd = cq & 63;
                #pragma unroll
                for (int rr = 0; rr < 2; rr++) {
                    int r = r0 + rr*8;
                    int bb = r >> 11, srow = r & (S_-1);
                    long long o = (((long long)(bb*H_ + hh))*S_ + srow)*HD_ + hd;
                    uint32_t hi, lo;
                    if (rr == 0) split_pair(c0, c1, hi, lo);
                    else         split_pair(c2, c3, hi, lo);
                    *(uint32_t*)(dh + o) = hi;
                    *(uint32_t*)(dl + o) = lo;
                }
            } else {
                float2 bv = *(const float2*)(bias0 + col);
                c0 += bv.x; c1 += bv.y; c2 += bv.x; c3 += bv.y;
                if (EPI == EPI_RESID) {
                    float2 r0v = *(const float2*)(resid + (long long)r0*N + col);
                    float2 r1v = *(const float2*)(resid + (long long)(r0+8)*N + col);
                    *(float2*)(Cf + (long long)r0*N + col)     = make_float2(c0 + r0v.x, c1 + r0v.y);
                    *(float2*)(Cf + (long long)(r0+8)*N + col) = make_float2(c2 + r1v.x, c3 + r1v.y);
                } else { // GELU -> bf16 hi/lo
                    c0 = 0.5f*c0*(1.0f + erff(c0*0.70710678118654752f));
                    c1 = 0.5f*c1*(1.0f + erff(c1*0.70710678118654752f));
                    c2 = 0.5f*c2*(1.0f + erff(c2*0.70710678118654752f));
                    c3 = 0.5f*c3*(1.0f + erff(c3*0.70710678118654752f));
                    uint32_t hi, lo;
                    split_pair(c0, c1, hi, lo);
                    *(uint32_t*)(Oh + (long long)r0*N + col) = hi;
                    *(uint32_t*)(Ol + (long long)r0*N + col) = lo;
                    split_pair(c2, c3, hi, lo);
                    *(uint32_t*)(Oh + (long long)(r0+8)*N + col) = hi;
                    *(uint32_t*)(Ol + (long long)(r0+8)*N + col) = lo;
                }
            }
        }
    }
}

// ================= HMMA flash attention (bf16-split) ========================
// Q-tile 64, key-tile 64, 4 warps (16 q-rows each).
#define ATT_SMEM (16384 + 2*32768)

__global__ __launch_bounds__(128) void attn_mma_kernel(
    const __nv_bfloat16* __restrict__ Qh, const __nv_bfloat16* __restrict__ Ql,
    const __nv_bfloat16* __restrict__ Kh, const __nv_bfloat16* __restrict__ Kl,
    const __nv_bfloat16* __restrict__ Vh, const __nv_bfloat16* __restrict__ Vl,
    const float* __restrict__ bias,
    __nv_bfloat16* __restrict__ Ohi, __nv_bfloat16* __restrict__ Olo)
{
    extern __shared__ char smc[];
    const uint32_t sb = smem_u32(smc);
    const int t = threadIdx.x, lane = t & 31, w = t >> 5;
    const int q0 = blockIdx.x*64, hh = blockIdx.y, bb = blockIdx.z;
    const long long bhs = (long long)(bb*H_ + hh)*S_;
    const int lr = lane >> 2, lc = (lane & 3)*2;

    // Q prologue load (2 tiles x 512 chunks16)
    #pragma unroll
    for (int i = 0; i < 8; i++) {
        int gid = t + i*128;
        int tile = gid >> 9, idx = gid & 511;
        int row = idx >> 3, c = idx & 7;
        const __nv_bfloat16* sp = tile ? Ql : Qh;
        const __nv_bfloat16* src = sp + (bhs + q0 + row)*HD_ + c*8;
        uint32_t dst = sb + tile*8192 + row*128 + ((c ^ (row & 7)) << 4);
        CP_ASYNC16(dst, src);
    }
    CP_COMMIT();

    auto ld_stage = [&](int st, int kt) {
        uint32_t base = sb + 16384 + st*32768;
        #pragma unroll
        for (int i = 0; i < 16; i++) {
            int gid = t + i*128;
            int tile = gid >> 9, idx = gid & 511;
            int row = idx >> 3, c = idx & 7;
            const __nv_bfloat16* sp = (tile == 0) ? Kh : (tile == 1) ? Kl
                                     : (tile == 2) ? Vh : Vl;
            const __nv_bfloat16* src = sp + (bhs + kt*64 + row)*HD_ + c*8;
            uint32_t dst = base + tile*8192 + row*128 + ((c ^ (row & 7)) << 4);
            CP_ASYNC16(dst, src);
        }
    };
    ld_stage(0, 0);
    CP_COMMIT();
    CP_WAIT(1);
    __syncthreads();

    // Q frags (persistent)
    uint32_t qfh[4][4], qfl[4][4];
    #pragma unroll
    for (int ks = 0; ks < 4; ks++) {
        int row = w*16 + (lane & 15);
        int ch  = ks*2 + (lane >> 4);
        uint32_t off = row*128 + ((ch ^ (row & 7)) << 4);
        ldsm_x4(qfh[ks], sb + off);
        ldsm_x4(qfl[ks], sb + 8192 + off);
    }

    float Oacc[8][4];
    #pragma unroll
    for (int nf = 0; nf < 8; nf++)
        #pragma unroll
        for (int j = 0; j < 4; j++) Oacc[nf][j] = 0.f;
    float ms0 = -3e38f, ms1 = -3e38f, ls0 = 0.f, ls1 = 0.f;

    const int NT = S_/64;
    for (int kt = 0; kt < NT; kt++) {
        if (kt + 1 < NT) { ld_stage((kt + 1) & 1, kt + 1); CP_COMMIT(); CP_WAIT(1); }
        else             { CP_WAIT(0); }
        __syncthreads();
        uint32_t base = sb + 16384 + (kt & 1)*32768;

        // S = Q @ K^T (3-product split)
        float sacc[8][4];
        #pragma unroll
        for (int nf = 0; nf < 8; nf++)
            #pragma unroll
            for (int j = 0; j < 4; j++) sacc[nf][j] = 0.f;
        #pragma unroll
        for (int ks = 0; ks < 4; ks++) {
            uint32_t kh4[4][4], kl4[4][4];
            #pragma unroll
            for (int g = 0; g < 4; g++) {
                int row = g*16 + (lane & 7) + ((lane & 16) >> 1);
                int ch  = ks*2 + ((lane >> 3) & 1);
                uint32_t off = row*128 + ((ch ^ (row & 7)) << 4);
                ldsm_x4(kh4[g], base + off);
                ldsm_x4(kl4[g], base + 8192 + off);
            }
            #pragma unroll
            for (int g = 0; g < 4; g++) {
                mma16816(sacc[2*g],   qfh[ks], &kh4[g][0]);
                mma16816(sacc[2*g+1], qfh[ks], &kh4[g][2]);
                mma16816(sacc[2*g],   qfh[ks], &kl4[g][0]);
                mma16816(sacc[2*g+1], qfh[ks], &kl4[g][2]);
                mma16816(sacc[2*g],   qfl[ks], &kh4[g][0]);
                mma16816(sacc[2*g+1], qfl[ks], &kh4[g][2]);
            }
        }

        // bias + scale, row maxes
        int r0 = q0 + w*16 + lr;
        const float* bp0 = bias + ((long long)bb*S_ + r0)*S_ + kt*64 + lc;
        const float* bp1 = bp0 + 8*S_;
        float rm0 = -3e38f, rm1 = -3e38f;
        #pragma unroll
        for (int nf = 0; nf < 8; nf++) {
            float2 b0 = *(const float2*)(bp0 + nf*8);
            float2 b1 = *(const float2*)(bp1 + nf*8);
            sacc[nf][0] = sacc[nf][0]*0.125f + b0.x;
            sacc[nf][1] = sacc[nf][1]*0.125f + b0.y;
            sacc[nf][2] = sacc[nf][2]*0.125f + b1.x;
            sacc[nf][3] = sacc[nf][3]*0.125f + b1.y;
            rm0 = fmaxf(rm0, fmaxf(sacc[nf][0], sacc[nf][1]));
            rm1 = fmaxf(rm1, fmaxf(sacc[nf][2], sacc[nf][3]));
        }
        rm0 = fmaxf(rm0, __shfl_xor_sync(0xffffffffu, rm0, 1));
        rm0 = fmaxf(rm0, __shfl_xor_sync(0xffffffffu, rm0, 2));
        rm1 = fmaxf(rm1, __shfl_xor_sync(0xffffffffu, rm1, 1));
        rm1 = fmaxf(rm1, __shfl_xor_sync(0xffffffffu, rm1, 2));
        float mn0 = fmaxf(ms0, rm0), mn1 = fmaxf(ms1, rm1);
        float al0 = __expf(ms0 - mn0), al1 = __expf(ms1 - mn1);
        ms0 = mn0; ms1 = mn1;
        float rs0 = 0.f, rs1 = 0.f;
        #pragma unroll
        for (int nf = 0; nf < 8; nf++) {
            sacc[nf][0] = __expf(sacc[nf][0] - mn0);
            sacc[nf][1] = __expf(sacc[nf][1] - mn0);
            sacc[nf][2] = __expf(sacc[nf][2] - mn1);
            sacc[nf][3] = __expf(sacc[nf][3] - mn1);
            rs0 += sacc[nf][0] + sacc[nf][1];
            rs1 += sacc[nf][2] + sacc[nf][3];
        }
        rs0 += __shfl_xor_sync(0xffffffffu, rs0, 1);
        rs0 += __shfl_xor_sync(0xffffffffu, rs0, 2);
        rs1 += __shfl_xor_sync(0xffffffffu, rs1, 1);
        rs1 += __shfl_xor_sync(0xffffffffu, rs1, 2);
        ls0 = ls0*al0 + rs0;
        ls1 = ls1*al1 + rs1;
        #pragma unroll
        for (int nf = 0; nf < 8; nf++) {
            Oacc[nf][0] *= al0; Oacc[nf][1] *= al0;
            Oacc[nf][2] *= al1; Oacc[nf][3] *= al1;
        }

        // P -> bf16 hi/lo frags (register transpose-free: C-frag == A-frag layout)
        uint32_t ph[4][4], pl[4][4];
        #pragma unroll
        for (int j = 0; j < 4; j++) {
            split_pair(sacc[2*j][0],   sacc[2*j][1],   ph[j][0], pl[j][0]);
            split_pair(sacc[2*j][2],   sacc[2*j][3],   ph[j][1], pl[j][1]);
            split_pair(sacc[2*j+1][0], sacc[2*j+1][1], ph[j][2], pl[j][2]);
            split_pair(sacc[2*j+1][2], sacc[2*j+1][3], ph[j][3], pl[j][3]);
        }

        // O += P @ V (3-product split), V via trans ldmatrix
        #pragma unroll
        for (int j = 0; j < 4; j++) {
            uint32_t vh4[4][4], vl4[4][4];
            #pragma unroll
            for (int g = 0; g < 4; g++) {
                int row = j*16 + (lane & 7) + (lane & 8);
                int ch  = g*2 + ((lane >> 4) & 1);
                uint32_t off = row*128 + ((ch ^ (row & 7)) << 4);
                ldsm_x4_t(vh4[g], base + 16384 + off);
                ldsm_x4_t(vl4[g], base + 24576 + off);
            }
            #pragma unroll
            for (int g = 0; g < 4; g++) {
                mma16816(Oacc[2*g],   ph[j], &vh4[g][0]);
                mma16816(Oacc[2*g+1], ph[j], &vh4[g][2]);
                mma16816(Oacc[2*g],   ph[j], &vl4[g][0]);
                mma16816(Oacc[2*g+1], ph[j], &vl4[g][2]);
                mma16816(Oacc[2*g],   pl[j], &vh4[g][0]);
                mma16816(Oacc[2*g+1], pl[j], &vh4[g][2]);
            }
        }
        __syncthreads();
    }

    // epilogue -> bf16 hi/lo into [B,S,D]
    float inv0 = 1.0f/ls0, inv1 = 1.0f/ls1;
    long long rowA = ((long long)bb*S_ + q0 + w*16 + lr)*D_ + hh*HD_;
    long long rowB = rowA + 8LL*D_;
    #pragma unroll
    for (int nf = 0; nf < 8; nf++) {
        int hd = nf*8 + lc;
        uint32_t hi, lo;
        split_pair(Oacc[nf][0]*inv0, Oacc[nf][1]*inv0, hi, lo);
        *(uint32_t*)(Ohi + rowA + hd) = hi;
        *(uint32_t*)(Olo + rowA + hd) = lo;
        split_pair(Oacc[nf][2]*inv1, Oacc[nf][3]*inv1, hi, lo);
        *(uint32_t*)(Ohi + rowB + hd) = hi;
        *(uint32_t*)(Olo + rowB + hd) = lo;
    }
}

// ---------------------------- launch ---------------------------------------
extern "C" void kernel_launch(void* const* d_in, const int* in_sizes, int n_in,
                              void* d_out, int out_size)
{
    const float* x    = (const float*)d_in[0];
    const int*   adj  = (const int*)  d_in[1];
    const float* edge = (const float*)d_in[2];
    const float* ln1g = (const float*)d_in[3];
    const float* ln1b = (const float*)d_in[4];
    const float* ln2g = (const float*)d_in[5];
    const float* ln2b = (const float*)d_in[6];
    const float* wq = (const float*)d_in[7];  const float* bq = (const float*)d_in[8];
    const float* wk = (const float*)d_in[9];  const float* bk = (const float*)d_in[10];
    const float* wv = (const float*)d_in[11]; const float* bv = (const float*)d_in[12];
    const float* wo = (const float*)d_in[13]; const float* bo = (const float*)d_in[14];
    const float* w1 = (const float*)d_in[15]; const float* b1 = (const float*)d_in[16];
    const float* w2 = (const float*)d_in[17]; const float* b2 = (const float*)d_in[18];
    float* out = (float*)d_out;

    float *x1, *biasc;
    cudaGetSymbolAddress((void**)&x1,    g_x1);
    cudaGetSymbolAddress((void**)&biasc, g_bias);
    __nv_bfloat16 *pah, *pal, *qah, *qal;
    __nv_bfloat16 *qh, *ql, *kh, *kl, *vh, *vl;
    __nv_bfloat16 *wqkvh, *wqkvl, *woh, *wol, *w1h, *w1l, *w2h, *w2l;
    cudaGetSymbolAddress((void**)&pah, g_pa_hi); cudaGetSymbolAddress((void**)&pal, g_pa_lo);
    cudaGetSymbolAddress((void**)&qah, g_qa_hi); cudaGetSymbolAddress((void**)&qal, g_qa_lo);
    cudaGetSymbolAddress((void**)&qh, g_qh); cudaGetSymbolAddress((void**)&ql, g_ql);
    cudaGetSymbolAddress((void**)&kh, g_kh); cudaGetSymbolAddress((void**)&kl, g_kl);
    cudaGetSymbolAddress((void**)&vh, g_vh); cudaGetSymbolAddress((void**)&vl, g_vl);
    cudaGetSymbolAddress((void**)&wqkvh, g_wqkv_hi); cudaGetSymbolAddress((void**)&wqkvl, g_wqkv_lo);
    cudaGetSymbolAddress((void**)&woh, g_wo_hi); cudaGetSymbolAddress((void**)&wol, g_wo_lo);
    cudaGetSymbolAddress((void**)&w1h, g_w1_hi); cudaGetSymbolAddress((void**)&w1l, g_w1_lo);
    cudaGetSymbolAddress((void**)&w2h, g_w2_hi); cudaGetSymbolAddress((void**)&w2l, g_w2_lo);

    cudaFuncSetAttribute(mma_gemm<EPI_QKV>,
        cudaFuncAttributeMaxDynamicSharedMemorySize, GEMM_SMEM);
    cudaFuncSetAttribute(mma_gemm<EPI_RESID>,
        cudaFuncAttributeMaxDynamicSharedMemorySize, GEMM_SMEM);
    cudaFuncSetAttribute(mma_gemm<EPI_GELU>,
        cudaFuncAttributeMaxDynamicSharedMemorySize, GEMM_SMEM);
    cudaFuncSetAttribute(attn_mma_kernel,
        cudaFuncAttributeMaxDynamicSharedMemorySize, ATT_SMEM);

    // 0) combined attention bias + weight transpose/split
    bias_kernel<<<(B_*S_*S_/4)/256, 256>>>((const int4*)adj, (const float4*)edge,
                                           (float4*)biasc);
    dim3 wb(256);
    wconvT_kernel<<<dim3(16,16), wb>>>(wq, wqkvh,           wqkvl,           D_, D_);
    wconvT_kernel<<<dim3(16,16), wb>>>(wk, wqkvh + D_*D_,   wqkvl + D_*D_,   D_, D_);
    wconvT_kernel<<<dim3(16,16), wb>>>(wv, wqkvh + 2*D_*D_, wqkvl + 2*D_*D_, D_, D_);
    wconvT_kernel<<<dim3(16,16), wb>>>(wo, woh, wol, D_, D_);
    wconvT_kernel<<<dim3(64,16), wb>>>(w1, w1h, w1l, D_, DFF);
    wconvT_kernel<<<dim3(16,64), wb>>>(w2, w2h, w2l, DFF, D_);

    // 1) LN1 -> bf16 split
    ln_bf16_kernel<<<MTOK, 256>>>(x, ln1g, ln1b, pah, pal);

    // 2) fused QKV projection -> q/k/v bf16 split [B,H,S,HD]
    mma_gemm<EPI_QKV><<<dim3(12, 32), 256, GEMM_SMEM>>>(
        pah, pal, wqkvh, wqkvl, bq, bk, bv, nullptr, nullptr,
        nullptr, nullptr, qh, ql, kh, kl, vh, vl, MTOK, 3*D_, D_);

    // 3) masked flash attention -> bf16 split [B,S,D]
    attn_mma_kernel<<<dim3(S_/64, H_, B_), 128, ATT_SMEM>>>(
        qh, ql, kh, kl, vh, vl, biasc, pah, pal);

    // 4) O projection + residual -> x1 (fp32)
    mma_gemm<EPI_RESID><<<dim3(4, 32), 256, GEMM_SMEM>>>(
        pah, pal, woh, wol, bo, nullptr, nullptr, x, x1,
        nullptr, nullptr, nullptr, nullptr, nullptr, nullptr, nullptr, nullptr,
        MTOK, D_, D_);

    // 5) LN2 -> bf16 split
    ln_bf16_kernel<<<MTOK, 256>>>(x1, ln2g, ln2b, pah, pal);

    // 6) MLP up + exact GELU -> bf16 split
    mma_gemm<EPI_GELU><<<dim3(16, 32), 256, GEMM_SMEM>>>(
        pah, pal, w1h, w1l, b1, nullptr, nullptr, nullptr, nullptr,
        qah, qal, nullptr, nullptr, nullptr, nullptr, nullptr, nullptr,
        MTOK, DFF, D_);

    // 7) MLP down + residual -> out
    mma_gemm<EPI_RESID><<<dim3(4, 32), 256, GEMM_SMEM>>>(
        qah, qal, w2h, w2l, b2, nullptr, nullptr, x1, out,
        nullptr, nullptr, nullptr, nullptr, nullptr, nullptr, nullptr, nullptr,
        MTOK, D_, DFF);
}

// round 4
// speedup vs baseline: 3.9063x; 1.1101x over previous
#include <cuda_runtime.h>
#include <cuda_fp16.h>
#include <math.h>
#include <cstdint>

#define B_   2
#define S_   2048
#define D_   512
#define H_   8
#define HD_  64
#define MTOK (B_*S_)      // 4096
#define DFF  (4*D_)       // 2048

// ---------------- scratch (device globals; no allocation allowed) ----------
__device__ float g_x1  [MTOK*D_];
__device__ float g_bias[(long long)B_*S_*S_];          // combined mask+edge bias

// fp16 split activation buffers
__device__ __half g_pa_hi[MTOK*D_];             // nx / att / n2
__device__ __half g_pa_lo[MTOK*D_];
__device__ __half g_qa_hi[MTOK*DFF];            // mlp hidden
__device__ __half g_qa_lo[MTOK*DFF];

// q hi/lo, k/v hi-only, [B,H,S,HD]
__device__ __half g_qh[MTOK*D_], g_ql[MTOK*D_];
__device__ __half g_kh[MTOK*D_];
__device__ __half g_vh[MTOK*D_];

// fp16 split transposed weights [N][K]
__device__ __half g_wqkv_hi[3*D_*D_], g_wqkv_lo[3*D_*D_];
__device__ __half g_wo_hi[D_*D_],    g_wo_lo[D_*D_];
__device__ __half g_w1_hi[DFF*D_],   g_w1_lo[DFF*D_];
__device__ __half g_w2_hi[D_*DFF],   g_w2_lo[D_*DFF];

// ======================= PTX helpers ========================================
__device__ __forceinline__ uint32_t smem_u32(const void* p) {
    uint32_t a;
    asm("{ .reg .u64 t; cvta.to.shared.u64 t, %1; cvt.u32.u64 %0, t; }"
        : "=r"(a) : "l"(p));
    return a;
}
#define CP_ASYNC16(dst, src) \
    asm volatile("cp.async.cg.shared.global [%0], [%1], 16;" :: "r"(dst), "l"(src))
#define CP_COMMIT() asm volatile("cp.async.commit_group;" ::: "memory")
#define CP_WAIT(n)  asm volatile("cp.async.wait_group %0;" :: "n"(n) : "memory")

__device__ __forceinline__ void ldsm_x4(uint32_t* r, uint32_t a) {
    asm volatile("ldmatrix.sync.aligned.m8n8.x4.shared.b16 {%0,%1,%2,%3}, [%4];"
        : "=r"(r[0]), "=r"(r[1]), "=r"(r[2]), "=r"(r[3]) : "r"(a));
}
__device__ __forceinline__ void ldsm_x4_t(uint32_t* r, uint32_t a) {
    asm volatile("ldmatrix.sync.aligned.m8n8.x4.trans.shared.b16 {%0,%1,%2,%3}, [%4];"
        : "=r"(r[0]), "=r"(r[1]), "=r"(r[2]), "=r"(r[3]) : "r"(a));
}
__device__ __forceinline__ void mma16816(float* c, const uint32_t* a, const uint32_t* b) {
    asm volatile("mma.sync.aligned.m16n8k16.row.col.f32.f16.f16.f32 "
        "{%0,%1,%2,%3}, {%4,%5,%6,%7}, {%8,%9}, {%0,%1,%2,%3};"
        : "+f"(c[0]), "+f"(c[1]), "+f"(c[2]), "+f"(c[3])
        : "r"(a[0]), "r"(a[1]), "r"(a[2]), "r"(a[3]), "r"(b[0]), "r"(b[1]));
}
__device__ __forceinline__ uint32_t packh(__half a, __half b) {
    return ((uint32_t)*(uint16_t*)&a) | ((uint32_t)*(uint16_t*)&b << 16);
}
__device__ __forceinline__ void split_pair(float a, float b, uint32_t& hi, uint32_t& lo) {
    __half ha = __float2half_rn(a), hb = __float2half_rn(b);
    __half la = __float2half_rn(a - __half2float(ha));
    __half lb = __float2half_rn(b - __half2float(hb));
    hi = packh(ha, hb);
    lo = packh(la, lb);
}

// ---------------- bias precompute: adj/edge -> combined fp32 ----------------
__global__ __launch_bounds__(256) void bias_kernel(
    const int4* __restrict__ adj, const float4* __restrict__ edge,
    float4* __restrict__ out)
{
    int i = blockIdx.x*256 + threadIdx.x;
    int4 a = adj[i]; float4 e = edge[i]; float4 o;
    o.x = a.x ? 0.1f*e.x : -1e30f;
    o.y = a.y ? 0.1f*e.y : -1e30f;
    o.z = a.z ? 0.1f*e.z : -1e30f;
    o.w = a.w ? 0.1f*e.w : -1e30f;
    out[i] = o;
}

// ---------------- LayerNorm -> fp16 hi/lo split -----------------------------
__global__ __launch_bounds__(256) void ln_f16_kernel(
    const float* __restrict__ x, const float* __restrict__ g,
    const float* __restrict__ b, __half* __restrict__ ohi,
    __half* __restrict__ olo)
{
    int row = blockIdx.x;
    const float2 v = ((const float2*)(x + (long long)row*D_))[threadIdx.x];
    float s  = v.x + v.y;
    float ss = v.x*v.x + v.y*v.y;
    #pragma unroll
    for (int o = 16; o; o >>= 1) {
        s  += __shfl_xor_sync(0xffffffffu, s,  o);
        ss += __shfl_xor_sync(0xffffffffu, ss, o);
    }
    __shared__ float sm_s[8], sm_ss[8];
    int w = threadIdx.x >> 5, l = threadIdx.x & 31;
    if (l == 0) { sm_s[w] = s; sm_ss[w] = ss; }
    __syncthreads();
    float ts = 0.f, tss = 0.f;
    #pragma unroll
    for (int i = 0; i < 8; i++) { ts += sm_s[i]; tss += sm_ss[i]; }
    float mu  = ts * (1.0f/D_);
    float var = tss * (1.0f/D_) - mu*mu;
    float inv = rsqrtf(var + 1e-5f);
    float2 gg = ((const float2*)g)[threadIdx.x];
    float2 bb = ((const float2*)b)[threadIdx.x];
    float ox = (v.x - mu)*inv*gg.x + bb.x;
    float oy = (v.y - mu)*inv*gg.y + bb.y;
    uint32_t hi, lo;
    split_pair(ox, oy, hi, lo);
    *(uint32_t*)(ohi + (long long)row*D_ + threadIdx.x*2) = hi;
    *(uint32_t*)(olo + (long long)row*D_ + threadIdx.x*2) = lo;
}

// ---------------- weight transpose + split: W[K,N] -> T[N,K] hi/lo ----------
__global__ __launch_bounds__(256) void wconvT_kernel(
    const float* __restrict__ W, __half* __restrict__ Thi,
    __half* __restrict__ Tlo, int K, int N)
{
    __shared__ float t[32][33];
    int tx = threadIdx.x & 31, ty = threadIdx.x >> 5;
    int k0 = blockIdx.y*32, n0 = blockIdx.x*32;
    #pragma unroll
    for (int i = 0; i < 4; i++)
        t[ty + i*8][tx] = W[(long long)(k0 + ty + i*8)*N + n0 + tx];
    __syncthreads();
    #pragma unroll
    for (int i = 0; i < 4; i++) {
        int n = n0 + ty + i*8, k = k0 + tx;
        float v = t[tx][ty + i*8];
        __half h = __float2half_rn(v);
        Thi[(long long)n*K + k] = h;
        Tlo[(long long)n*K + k] = __float2half_rn(v - __half2float(h));
    }
}

// ================= HMMA fp16-split GEMM: 128x128 blocks =====================
// C = A[M,K] @ B[N,K]^T ; A,B fp16 hi/lo; 3-product split; fp32 accum.
#define EPI_QKV   1
#define EPI_RESID 2
#define EPI_GELU  3
#define GEMM_SMEM 131072   // 2 stages x (4 tiles x 16KB)

template<int EPI>
__global__ __launch_bounds__(256) void mma_gemm(
    const __half* __restrict__ Ah, const __half* __restrict__ Al,
    const __half* __restrict__ Bh, const __half* __restrict__ Bl,
    const float* __restrict__ bias0, const float* __restrict__ bias1,
    const float* __restrict__ bias2, const float* __restrict__ resid,
    float* __restrict__ Cf,
    __half* __restrict__ Oh, __half* __restrict__ Ol,
    __half* __restrict__ qh_, __half* __restrict__ ql_,
    __half* __restrict__ kh_, __half* __restrict__ vh_,
    int M, int N, int K)
{
    extern __shared__ char smc[];
    const uint32_t sb = smem_u32(smc);
    const int t = threadIdx.x, lane = t & 31;
    const int wid = t >> 5, wm = wid & 3, wn = wid >> 2;
    const int m0 = blockIdx.y*128, n0 = blockIdx.x*128;

    float acc[2][8][4];
    #pragma unroll
    for (int f = 0; f < 2; f++)
        #pragma unroll
        for (int nf = 0; nf < 8; nf++)
            #pragma unroll
            for (int j = 0; j < 4; j++) acc[f][nf][j] = 0.f;

    auto ld_stage = [&](int st, int k0) {
        #pragma unroll
        for (int i = 0; i < 16; i++) {
            int gid = t + i*256;
            int tile = gid >> 10, idx = gid & 1023;
            int row = idx >> 3, c = idx & 7;
            const __half* sp = (tile == 0) ? Ah : (tile == 1) ? Al
                             : (tile == 2) ? Bh : Bl;
            long long grow = (long long)((tile < 2) ? m0 : n0) + row;
            const __half* src = sp + grow*K + k0 + c*8;
            uint32_t dst = sb + st*65536 + tile*16384 + row*128 + ((c ^ (row & 7)) << 4);
            CP_ASYNC16(dst, src);
        }
    };

    const int NS = K >> 6;
    ld_stage(0, 0);
    CP_COMMIT();
    for (int s = 0; s < NS; s++) {
        if (s + 1 < NS) { ld_stage((s + 1) & 1, (s + 1) << 6); CP_COMMIT(); CP_WAIT(1); }
        else            { CP_WAIT(0); }
        __syncthreads();
        uint32_t base = sb + (s & 1)*65536;
        #pragma unroll
        for (int ks = 0; ks < 4; ks++) {
            uint32_t ah[2][4], al[2][4];
            #pragma unroll
            for (int f = 0; f < 2; f++) {
                int row = wm*32 + f*16 + (lane & 15);
                int ch  = ks*2 + (lane >> 4);
                uint32_t off = row*128 + ((ch ^ (row & 7)) << 4);
                ldsm_x4(ah[f], base + off);
                ldsm_x4(al[f], base + 16384 + off);
            }
            uint32_t bh[4][4], bl[4][4];
            #pragma unroll
            for (int g = 0; g < 4; g++) {
                int row = wn*64 + g*16 + (lane & 7) + ((lane & 16) >> 1);
                int ch  = ks*2 + ((lane >> 3) & 1);
                uint32_t off = row*128 + ((ch ^ (row & 7)) << 4);
                ldsm_x4(bh[g], base + 32768 + off);
                ldsm_x4(bl[g], base + 49152 + off);
            }
            #pragma unroll
            for (int f = 0; f < 2; f++)
                #pragma unroll
                for (int g = 0; g < 4; g++) {
                    mma16816(acc[f][2*g],   ah[f], &bh[g][0]);
                    mma16816(acc[f][2*g+1], ah[f], &bh[g][2]);
                    mma16816(acc[f][2*g],   ah[f], &bl[g][0]);
                    mma16816(acc[f][2*g+1], ah[f], &bl[g][2]);
                    mma16816(acc[f][2*g],   al[f], &bh[g][0]);
                    mma16816(acc[f][2*g+1], al[f], &bh[g][2]);
                }
        }
        __syncthreads();
    }

    // epilogue
    const int lr = lane >> 2, lc = (lane & 3)*2;
    #pragma unroll
    for (int f = 0; f < 2; f++) {
        int r0 = m0 + wm*32 + f*16 + lr;
        #pragma unroll
        for (int nf = 0; nf < 8; nf++) {
            int col = n0 + wn*64 + nf*8 + lc;
            float c0 = acc[f][nf][0], c1 = acc[f][nf][1];
            float c2 = acc[f][nf][2], c3 = acc[f][nf][3];
            if (EPI == EPI_QKV) {
                int which = col >> 9, cq = col & 511;
                const float* bp = (which == 0) ? bias0 : (which == 1) ? bias1 : bias2;
                float2 bv = *(const float2*)(bp + cq);
                c0 += bv.x; c1 += bv.y; c2 += bv.x; c3 += bv.y;
                __half* dh = (which == 0) ? qh_ : (which == 1) ? kh_ : vh_;
                int hh = cq >> 6, hd = cq & 63;
                #pragma unroll
                for (int rr = 0; rr < 2; rr++) {
                    int r = r0 + rr*8;
                    int bb = r >> 11, srow = r & (S_-1);
                    long long o = (((long long)(bb*H_ + hh))*S_ + srow)*HD_ + hd;
                    uint32_t hi, lo;
                    if (rr == 0) split_pair(c0, c1, hi, lo);
                    else         split_pair(c2, c3, hi, lo);
                    *(uint32_t*)(dh + o) = hi;
                    if (which == 0) *(uint32_t*)(ql_ + o) = lo;  // only q needs lo
                }
            } else {
                float2 bv = *(const float2*)(bias0 + col);
                c0 += bv.x; c1 += bv.y; c2 += bv.x; c3 += bv.y;
                if (EPI == EPI_RESID) {
                    float2 r0v = *(const float2*)(resid + (long long)r0*N + col);
                    float2 r1v = *(const float2*)(resid + (long long)(r0+8)*N + col);
                    *(float2*)(Cf + (long long)r0*N + col)     = make_float2(c0 + r0v.x, c1 + r0v.y);
                    *(float2*)(Cf + (long long)(r0+8)*N + col) = make_float2(c2 + r1v.x, c3 + r1v.y);
                } else { // GELU -> fp16 hi/lo
                    c0 = 0.5f*c0*(1.0f + erff(c0*0.70710678118654752f));
                    c1 = 0.5f*c1*(1.0f + erff(c1*0.70710678118654752f));
                    c2 = 0.5f*c2*(1.0f + erff(c2*0.70710678118654752f));
                    c3 = 0.5f*c3*(1.0f + erff(c3*0.70710678118654752f));
                    uint32_t hi, lo;
                    split_pair(c0, c1, hi, lo);
                    *(uint32_t*)(Oh + (long long)r0*N + col) = hi;
                    *(uint32_t*)(Ol + (long long)r0*N + col) = lo;
                    split_pair(c2, c3, hi, lo);
                    *(uint32_t*)(Oh + (long long)(r0+8)*N + col) = hi;
                    *(uint32_t*)(Ol + (long long)(r0+8)*N + col) = lo;
                }
            }
        }
    }
}

// ================= HMMA flash attention (fp16, 2-product) ===================
// Q-tile 64, key-tile 64, 4 warps (16 q-rows each). K/V hi-only.
#define ATT_SMEM (16384 + 2*16384)

__global__ __launch_bounds__(128) void attn_mma_kernel(
    const __half* __restrict__ Qh, const __half* __restrict__ Ql,
    const __half* __restrict__ Kh, const __half* __restrict__ Vh,
    const float* __restrict__ bias,
    __half* __restrict__ Ohi, __half* __restrict__ Olo)
{
    extern __shared__ char smc[];
    const uint32_t sb = smem_u32(smc);
    const int t = threadIdx.x, lane = t & 31, w = t >> 5;
    const int q0 = blockIdx.x*64, hh = blockIdx.y, bb = blockIdx.z;
    const long long bhs = (long long)(bb*H_ + hh)*S_;
    const int lr = lane >> 2, lc = (lane & 3)*2;

    // Q prologue load (hi + lo tiles)
    #pragma unroll
    for (int i = 0; i < 8; i++) {
        int gid = t + i*128;
        int tile = gid >> 9, idx = gid & 511;
        int row = idx >> 3, c = idx & 7;
        const __half* sp = tile ? Ql : Qh;
        const __half* src = sp + (bhs + q0 + row)*HD_ + c*8;
        uint32_t dst = sb + tile*8192 + row*128 + ((c ^ (row & 7)) << 4);
        CP_ASYNC16(dst, src);
    }
    CP_COMMIT();

    auto ld_stage = [&](int st, int kt) {
        uint32_t base = sb + 16384 + st*16384;
        #pragma unroll
        for (int i = 0; i < 8; i++) {
            int gid = t + i*128;
            int tile = gid >> 9, idx = gid & 511;   // 0=Kh, 1=Vh
            int row = idx >> 3, c = idx & 7;
            const __half* sp = tile ? Vh : Kh;
            const __half* src = sp + (bhs + kt*64 + row)*HD_ + c*8;
            uint32_t dst = base + tile*8192 + row*128 + ((c ^ (row & 7)) << 4);
            CP_ASYNC16(dst, src);
        }
    };
    ld_stage(0, 0);
    CP_COMMIT();
    CP_WAIT(1);
    __syncthreads();

    // Q frags (persistent)
    uint32_t qfh[4][4], qfl[4][4];
    #pragma unroll
    for (int ks = 0; ks < 4; ks++) {
        int row = w*16 + (lane & 15);
        int ch  = ks*2 + (lane >> 4);
        uint32_t off = row*128 + ((ch ^ (row & 7)) << 4);
        ldsm_x4(qfh[ks], sb + off);
        ldsm_x4(qfl[ks], sb + 8192 + off);
    }

    float Oacc[8][4];
    #pragma unroll
    for (int nf = 0; nf < 8; nf++)
        #pragma unroll
        for (int j = 0; j < 4; j++) Oacc[nf][j] = 0.f;
    float ms0 = -3e38f, ms1 = -3e38f, ls0 = 0.f, ls1 = 0.f;

    const int NT = S_/64;
    for (int kt = 0; kt < NT; kt++) {
        if (kt + 1 < NT) { ld_stage((kt + 1) & 1, kt + 1); CP_COMMIT(); CP_WAIT(1); }
        else             { CP_WAIT(0); }
        __syncthreads();
        uint32_t base = sb + 16384 + (kt & 1)*16384;

        // S = Q @ K^T (2-product: Qh*Kh + Ql*Kh)
        float sacc[8][4];
        #pragma unroll
        for (int nf = 0; nf < 8; nf++)
            #pragma unroll
            for (int j = 0; j < 4; j++) sacc[nf][j] = 0.f;
        #pragma unroll
        for (int ks = 0; ks < 4; ks++) {
            uint32_t kh4[4][4];
            #pragma unroll
            for (int g = 0; g < 4; g++) {
                int row = g*16 + (lane & 7) + ((lane & 16) >> 1);
                int ch  = ks*2 + ((lane >> 3) & 1);
                uint32_t off = row*128 + ((ch ^ (row & 7)) << 4);
                ldsm_x4(kh4[g], base + off);
            }
            #pragma unroll
            for (int g = 0; g < 4; g++) {
                mma16816(sacc[2*g],   qfh[ks], &kh4[g][0]);
                mma16816(sacc[2*g+1], qfh[ks], &kh4[g][2]);
                mma16816(sacc[2*g],   qfl[ks], &kh4[g][0]);
                mma16816(sacc[2*g+1], qfl[ks], &kh4[g][2]);
            }
        }

        // bias + scale, row maxes
        int r0 = q0 + w*16 + lr;
        const float* bp0 = bias + ((long long)bb*S_ + r0)*S_ + kt*64 + lc;
        const float* bp1 = bp0 + 8*S_;
        float rm0 = -3e38f, rm1 = -3e38f;
        #pragma unroll
        for (int nf = 0; nf < 8; nf++) {
            float2 b0 = *(const float2*)(bp0 + nf*8);
            float2 b1 = *(const float2*)(bp1 + nf*8);
            sacc[nf][0] = sacc[nf][0]*0.125f + b0.x;
            sacc[nf][1] = sacc[nf][1]*0.125f + b0.y;
            sacc[nf][2] = sacc[nf][2]*0.125f + b1.x;
            sacc[nf][3] = sacc[nf][3]*0.125f + b1.y;
            rm0 = fmaxf(rm0, fmaxf(sacc[nf][0], sacc[nf][1]));
            rm1 = fmaxf(rm1, fmaxf(sacc[nf][2], sacc[nf][3]));
        }
        rm0 = fmaxf(rm0, __shfl_xor_sync(0xffffffffu, rm0, 1));
        rm0 = fmaxf(rm0, __shfl_xor_sync(0xffffffffu, rm0, 2));
        rm1 = fmaxf(rm1, __shfl_xor_sync(0xffffffffu, rm1, 1));
        rm1 = fmaxf(rm1, __shfl_xor_sync(0xffffffffu, rm1, 2));
        float mn0 = fmaxf(ms0, rm0), mn1 = fmaxf(ms1, rm1);
        float al0 = __expf(ms0 - mn0), al1 = __expf(ms1 - mn1);
        ms0 = mn0; ms1 = mn1;
        float rs0 = 0.f, rs1 = 0.f;
        #pragma unroll
        for (int nf = 0; nf < 8; nf++) {
            sacc[nf][0] = __expf(sacc[nf][0] - mn0);
            sacc[nf][1] = __expf(sacc[nf][1] - mn0);
            sacc[nf][2] = __expf(sacc[nf][2] - mn1);
            sacc[nf][3] = __expf(sacc[nf][3] - mn1);
            rs0 += sacc[nf][0] + sacc[nf][1];
            rs1 += sacc[nf][2] + sacc[nf][3];
        }
        rs0 += __shfl_xor_sync(0xffffffffu, rs0, 1);
        rs0 += __shfl_xor_sync(0xffffffffu, rs0, 2);
        rs1 += __shfl_xor_sync(0xffffffffu, rs1, 1);
        rs1 += __shfl_xor_sync(0xffffffffu, rs1, 2);
        ls0 = ls0*al0 + rs0;
        ls1 = ls1*al1 + rs1;
        #pragma unroll
        for (int nf = 0; nf < 8; nf++) {
            Oacc[nf][0] *= al0; Oacc[nf][1] *= al0;
            Oacc[nf][2] *= al1; Oacc[nf][3] *= al1;
        }

        // P -> fp16 hi/lo frags (C-frag layout == A-frag layout)
        uint32_t ph[4][4], pl[4][4];
        #pragma unroll
        for (int j = 0; j < 4; j++) {
            split_pair(sacc[2*j][0],   sacc[2*j][1],   ph[j][0], pl[j][0]);
            split_pair(sacc[2*j][2],   sacc[2*j][3],   ph[j][1], pl[j][1]);
            split_pair(sacc[2*j+1][0], sacc[2*j+1][1], ph[j][2], pl[j][2]);
            split_pair(sacc[2*j+1][2], sacc[2*j+1][3], ph[j][3], pl[j][3]);
        }

        // O += P @ V (2-product: Ph*Vh + Pl*Vh), V via trans ldmatrix
        #pragma unroll
        for (int j = 0; j < 4; j++) {
            uint32_t vh4[4][4];
            #pragma unroll
            for (int g = 0; g < 4; g++) {
                int row = j*16 + (lane & 7) + (lane & 8);
                int ch  = g*2 + ((lane >> 4) & 1);
                uint32_t off = row*128 + ((ch ^ (row & 7)) << 4);
                ldsm_x4_t(vh4[g], base + 8192 + off);
            }
            #pragma unroll
            for (int g = 0; g < 4; g++) {
                mma16816(Oacc[2*g],   ph[j], &vh4[g][0]);
                mma16816(Oacc[2*g+1], ph[j], &vh4[g][2]);
                mma16816(Oacc[2*g],   pl[j], &vh4[g][0]);
                mma16816(Oacc[2*g+1], pl[j], &vh4[g][2]);
            }
        }
        __syncthreads();
    }

    // epilogue -> fp16 hi/lo into [B,S,D]
    float inv0 = 1.0f/ls0, inv1 = 1.0f/ls1;
    long long rowA = ((long long)bb*S_ + q0 + w*16 + lr)*D_ + hh*HD_;
    long long rowB = rowA + 8LL*D_;
    #pragma unroll
    for (int nf = 0; nf < 8; nf++) {
        int hd = nf*8 + lc;
        uint32_t hi, lo;
        split_pair(Oacc[nf][0]*inv0, Oacc[nf][1]*inv0, hi, lo);
        *(uint32_t*)(Ohi + rowA + hd) = hi;
        *(uint32_t*)(Olo + rowA + hd) = lo;
        split_pair(Oacc[nf][2]*inv1, Oacc[nf][3]*inv1, hi, lo);
        *(uint32_t*)(Ohi + rowB + hd) = hi;
        *(uint32_t*)(Olo + rowB + hd) = lo;
    }
}

// ---------------------------- launch ---------------------------------------
extern "C" void kernel_launch(void* const* d_in, const int* in_sizes, int n_in,
                              void* d_out, int out_size)
{
    const float* x    = (const float*)d_in[0];
    const int*   adj  = (const int*)  d_in[1];
    const float* edge = (const float*)d_in[2];
    const float* ln1g = (const float*)d_in[3];
    const float* ln1b = (const float*)d_in[4];
    const float* ln2g = (const float*)d_in[5];
    const float* ln2b = (const float*)d_in[6];
    const float* wq = (const float*)d_in[7];  const float* bq = (const float*)d_in[8];
    const float* wk = (const float*)d_in[9];  const float* bk = (const float*)d_in[10];
    const float* wv = (const float*)d_in[11]; const float* bv = (const float*)d_in[12];
    const float* wo = (const float*)d_in[13]; const float* bo = (const float*)d_in[14];
    const float* w1 = (const float*)d_in[15]; const float* b1 = (const float*)d_in[16];
    const float* w2 = (const float*)d_in[17]; const float* b2 = (const float*)d_in[18];
    float* out = (float*)d_out;

    float *x1, *biasc;
    cudaGetSymbolAddress((void**)&x1,    g_x1);
    cudaGetSymbolAddress((void**)&biasc, g_bias);
    __half *pah, *pal, *qah, *qal;
    __half *qh, *ql, *kh, *vh;
    __half *wqkvh, *wqkvl, *woh, *wol, *w1h, *w1l, *w2h, *w2l;
    cudaGetSymbolAddress((void**)&pah, g_pa_hi); cudaGetSymbolAddress((void**)&pal, g_pa_lo);
    cudaGetSymbolAddress((void**)&qah, g_qa_hi); cudaGetSymbolAddress((void**)&qal, g_qa_lo);
    cudaGetSymbolAddress((void**)&qh, g_qh); cudaGetSymbolAddress((void**)&ql, g_ql);
    cudaGetSymbolAddress((void**)&kh, g_kh); cudaGetSymbolAddress((void**)&vh, g_vh);
    cudaGetSymbolAddress((void**)&wqkvh, g_wqkv_hi); cudaGetSymbolAddress((void**)&wqkvl, g_wqkv_lo);
    cudaGetSymbolAddress((void**)&woh, g_wo_hi); cudaGetSymbolAddress((void**)&wol, g_wo_lo);
    cudaGetSymbolAddress((void**)&w1h, g_w1_hi); cudaGetSymbolAddress((void**)&w1l, g_w1_lo);
    cudaGetSymbolAddress((void**)&w2h, g_w2_hi); cudaGetSymbolAddress((void**)&w2l, g_w2_lo);

    cudaFuncSetAttribute(mma_gemm<EPI_QKV>,
        cudaFuncAttributeMaxDynamicSharedMemorySize, GEMM_SMEM);
    cudaFuncSetAttribute(mma_gemm<EPI_RESID>,
        cudaFuncAttributeMaxDynamicSharedMemorySize, GEMM_SMEM);
    cudaFuncSetAttribute(mma_gemm<EPI_GELU>,
        cudaFuncAttributeMaxDynamicSharedMemorySize, GEMM_SMEM);
    cudaFuncSetAttribute(attn_mma_kernel,
        cudaFuncAttributeMaxDynamicSharedMemorySize, ATT_SMEM);

    // side stream + events, created once (outside graph capture on first call)
    static cudaStream_t s1 = nullptr;
    static cudaEvent_t evFork = nullptr, evJoin = nullptr;
    if (!s1) {
        cudaStreamCreateWithFlags(&s1, cudaStreamNonBlocking);
        cudaEventCreateWithFlags(&evFork, cudaEventDisableTiming);
        cudaEventCreateWithFlags(&evJoin, cudaEventDisableTiming);
    }

    // fork: side stream does bias + wo/w1/w2 conversions
    cudaEventRecord(evFork, 0);
    cudaStreamWaitEvent(s1, evFork, 0);
    bias_kernel<<<(B_*S_*S_/4)/256, 256, 0, s1>>>(
        (const int4*)adj, (const float4*)edge, (float4*)biasc);
    dim3 wb(256);
    wconvT_kernel<<<dim3(16,16), wb, 0, s1>>>(wo, woh, wol, D_, D_);
    wconvT_kernel<<<dim3(64,16), wb, 0, s1>>>(w1, w1h, w1l, D_, DFF);
    wconvT_kernel<<<dim3(16,64), wb, 0, s1>>>(w2, w2h, w2l, DFF, D_);
    cudaEventRecord(evJoin, s1);

    // main: qkv weight conversions + LN1 + QKV gemm
    wconvT_kernel<<<dim3(16,16), wb>>>(wq, wqkvh,           wqkvl,           D_, D_);
    wconvT_kernel<<<dim3(16,16), wb>>>(wk, wqkvh + D_*D_,   wqkvl + D_*D_,   D_, D_);
    wconvT_kernel<<<dim3(16,16), wb>>>(wv, wqkvh + 2*D_*D_, wqkvl + 2*D_*D_, D_, D_);
    ln_f16_kernel<<<MTOK, 256>>>(x, ln1g, ln1b, pah, pal);
    mma_gemm<EPI_QKV><<<dim3(12, 32), 256, GEMM_SMEM>>>(
        pah, pal, wqkvh, wqkvl, bq, bk, bv, nullptr, nullptr,
        nullptr, nullptr, qh, ql, kh, vh, MTOK, 3*D_, D_);

    // join, then attention
    cudaStreamWaitEvent(0, evJoin, 0);
    attn_mma_kernel<<<dim3(S_/64, H_, B_), 128, ATT_SMEM>>>(
        qh, ql, kh, vh, biasc, pah, pal);

    // O projection + residual -> x1 (fp32)
    mma_gemm<EPI_RESID><<<dim3(4, 32), 256, GEMM_SMEM>>>(
        pah, pal, woh, wol, bo, nullptr, nullptr, x, x1,
        nullptr, nullptr, nullptr, nullptr, nullptr, nullptr, MTOK, D_, D_);

    // LN2 -> fp16 split
    ln_f16_kernel<<<MTOK, 256>>>(x1, ln2g, ln2b, pah, pal);

    // MLP up + exact GELU -> fp16 split
    mma_gemm<EPI_GELU><<<dim3(16, 32), 256, GEMM_SMEM>>>(
        pah, pal, w1h, w1l, b1, nullptr, nullptr, nullptr, nullptr,
        qah, qal, nullptr, nullptr, nullptr, nullptr, MTOK, DFF, D_);

    // MLP down + residual -> out
    mma_gemm<EPI_RESID><<<dim3(4, 32), 256, GEMM_SMEM>>>(
        qah, qal, w2h, w2l, b2, nullptr, nullptr, x1, out,
        nullptr, nullptr, nullptr, nullptr, nullptr, nullptr, MTOK, D_, DFF);
}

// round 5
// speedup vs baseline: 5.0459x; 1.2917x over previous
#include <cuda_runtime.h>
#include <cuda_fp16.h>
#include <math.h>
#include <cstdint>

#define B_   2
#define S_   2048
#define D_   512
#define H_   8
#define HD_  64
#define MTOK (B_*S_)      // 4096
#define DFF  (4*D_)       // 2048

// ---------------- scratch (device globals; no allocation allowed) ----------
__device__ float  g_x1  [MTOK*D_];
__device__ __half g_bias[(long long)B_*S_*S_];         // combined mask+edge bias (fp16)

// fp16 split activation buffers
__device__ __half g_pa_hi[MTOK*D_];             // nx / att / n2
__device__ __half g_pa_lo[MTOK*D_];
__device__ __half g_qa_hi[MTOK*DFF];            // mlp hidden
__device__ __half g_qa_lo[MTOK*DFF];

// q hi/lo, k/v hi-only, [B,H,S,HD]
__device__ __half g_qh[MTOK*D_], g_ql[MTOK*D_];
__device__ __half g_kh[MTOK*D_];
__device__ __half g_vh[MTOK*D_];

// fp16 transposed weights [N][K], hi-only
__device__ __half g_wqkv_hi[3*D_*D_];
__device__ __half g_wo_hi[D_*D_];
__device__ __half g_w1_hi[DFF*D_];
__device__ __half g_w2_hi[D_*DFF];

// ======================= PTX helpers ========================================
__device__ __forceinline__ uint32_t smem_u32(const void* p) {
    uint32_t a;
    asm("{ .reg .u64 t; cvta.to.shared.u64 t, %1; cvt.u32.u64 %0, t; }"
        : "=r"(a) : "l"(p));
    return a;
}
#define CP_ASYNC16(dst, src) \
    asm volatile("cp.async.cg.shared.global [%0], [%1], 16;" :: "r"(dst), "l"(src))
#define CP_COMMIT() asm volatile("cp.async.commit_group;" ::: "memory")
#define CP_WAIT(n)  asm volatile("cp.async.wait_group %0;" :: "n"(n) : "memory")

__device__ __forceinline__ void ldsm_x4(uint32_t* r, uint32_t a) {
    asm volatile("ldmatrix.sync.aligned.m8n8.x4.shared.b16 {%0,%1,%2,%3}, [%4];"
        : "=r"(r[0]), "=r"(r[1]), "=r"(r[2]), "=r"(r[3]) : "r"(a));
}
__device__ __forceinline__ void ldsm_x4_t(uint32_t* r, uint32_t a) {
    asm volatile("ldmatrix.sync.aligned.m8n8.x4.trans.shared.b16 {%0,%1,%2,%3}, [%4];"
        : "=r"(r[0]), "=r"(r[1]), "=r"(r[2]), "=r"(r[3]) : "r"(a));
}
__device__ __forceinline__ void mma16816(float* c, const uint32_t* a, const uint32_t* b) {
    asm volatile("mma.sync.aligned.m16n8k16.row.col.f32.f16.f16.f32 "
        "{%0,%1,%2,%3}, {%4,%5,%6,%7}, {%8,%9}, {%0,%1,%2,%3};"
        : "+f"(c[0]), "+f"(c[1]), "+f"(c[2]), "+f"(c[3])
        : "r"(a[0]), "r"(a[1]), "r"(a[2]), "r"(a[3]), "r"(b[0]), "r"(b[1]));
}
__device__ __forceinline__ uint32_t packh(__half a, __half b) {
    return ((uint32_t)*(uint16_t*)&a) | ((uint32_t)*(uint16_t*)&b << 16);
}
__device__ __forceinline__ uint32_t pack2(float a, float b) {
    return packh(__float2half_rn(a), __float2half_rn(b));
}
__device__ __forceinline__ void split_pair(float a, float b, uint32_t& hi, uint32_t& lo) {
    __half ha = __float2half_rn(a), hb = __float2half_rn(b);
    __half la = __float2half_rn(a - __half2float(ha));
    __half lb = __float2half_rn(b - __half2float(hb));
    hi = packh(ha, hb);
    lo = packh(la, lb);
}

// ---------------- bias precompute: adj/edge -> combined fp16 ----------------
__global__ __launch_bounds__(256) void bias_kernel(
    const int4* __restrict__ adj, const float4* __restrict__ edge,
    uint2* __restrict__ out)
{
    int i = blockIdx.x*256 + threadIdx.x;
    int4 a = adj[i]; float4 e = edge[i];
    uint2 o;
    o.x = pack2(a.x ? 0.1f*e.x : -60000.f, a.y ? 0.1f*e.y : -60000.f);
    o.y = pack2(a.z ? 0.1f*e.z : -60000.f, a.w ? 0.1f*e.w : -60000.f);
    out[i] = o;
}

// ---------------- LayerNorm -> fp16 hi/lo split -----------------------------
__global__ __launch_bounds__(256) void ln_f16_kernel(
    const float* __restrict__ x, const float* __restrict__ g,
    const float* __restrict__ b, __half* __restrict__ ohi,
    __half* __restrict__ olo)
{
    int row = blockIdx.x;
    const float2 v = ((const float2*)(x + (long long)row*D_))[threadIdx.x];
    float s  = v.x + v.y;
    float ss = v.x*v.x + v.y*v.y;
    #pragma unroll
    for (int o = 16; o; o >>= 1) {
        s  += __shfl_xor_sync(0xffffffffu, s,  o);
        ss += __shfl_xor_sync(0xffffffffu, ss, o);
    }
    __shared__ float sm_s[8], sm_ss[8];
    int w = threadIdx.x >> 5, l = threadIdx.x & 31;
    if (l == 0) { sm_s[w] = s; sm_ss[w] = ss; }
    __syncthreads();
    float ts = 0.f, tss = 0.f;
    #pragma unroll
    for (int i = 0; i < 8; i++) { ts += sm_s[i]; tss += sm_ss[i]; }
    float mu  = ts * (1.0f/D_);
    float var = tss * (1.0f/D_) - mu*mu;
    float inv = rsqrtf(var + 1e-5f);
    float2 gg = ((const float2*)g)[threadIdx.x];
    float2 bb = ((const float2*)b)[threadIdx.x];
    float ox = (v.x - mu)*inv*gg.x + bb.x;
    float oy = (v.y - mu)*inv*gg.y + bb.y;
    uint32_t hi, lo;
    split_pair(ox, oy, hi, lo);
    *(uint32_t*)(ohi + (long long)row*D_ + threadIdx.x*2) = hi;
    *(uint32_t*)(olo + (long long)row*D_ + threadIdx.x*2) = lo;
}

// ---------------- weight transpose: W[K,N] -> T[N,K] fp16 hi ---------------
__global__ __launch_bounds__(256) void wconvT_kernel(
    const float* __restrict__ W, __half* __restrict__ Thi, int K, int N)
{
    __shared__ float t[32][33];
    int tx = threadIdx.x & 31, ty = threadIdx.x >> 5;
    int k0 = blockIdx.y*32, n0 = blockIdx.x*32;
    #pragma unroll
    for (int i = 0; i < 4; i++)
        t[ty + i*8][tx] = W[(long long)(k0 + ty + i*8)*N + n0 + tx];
    __syncthreads();
    #pragma unroll
    for (int i = 0; i < 4; i++) {
        int n = n0 + ty + i*8, k = k0 + tx;
        Thi[(long long)n*K + k] = __float2half_rn(t[tx][ty + i*8]);
    }
}

// ================= HMMA fp16 2-product GEMM: 128x128 blocks =================
// C = (Ah+Al)[M,K] @ Bh[N,K]^T ; fp32 accum.
#define EPI_QKV   1
#define EPI_RESID 2
#define EPI_GELU  3
#define GEMM_SMEM 98304    // 2 stages x (3 tiles x 16KB)

template<int EPI>
__global__ __launch_bounds__(256) void mma_gemm(
    const __half* __restrict__ Ah, const __half* __restrict__ Al,
    const __half* __restrict__ Bh,
    const float* __restrict__ bias0, const float* __restrict__ bias1,
    const float* __restrict__ bias2, const float* __restrict__ resid,
    float* __restrict__ Cf,
    __half* __restrict__ Oh, __half* __restrict__ Ol,
    __half* __restrict__ qh_, __half* __restrict__ ql_,
    __half* __restrict__ kh_, __half* __restrict__ vh_,
    int M, int N, int K)
{
    extern __shared__ char smc[];
    const uint32_t sb = smem_u32(smc);
    const int t = threadIdx.x, lane = t & 31;
    const int wid = t >> 5, wm = wid & 3, wn = wid >> 2;
    const int m0 = blockIdx.y*128, n0 = blockIdx.x*128;

    float acc[2][8][4];
    #pragma unroll
    for (int f = 0; f < 2; f++)
        #pragma unroll
        for (int nf = 0; nf < 8; nf++)
            #pragma unroll
            for (int j = 0; j < 4; j++) acc[f][nf][j] = 0.f;

    auto ld_stage = [&](int st, int k0) {
        #pragma unroll
        for (int i = 0; i < 12; i++) {
            int gid = t + i*256;
            int tile = gid >> 10, idx = gid & 1023;
            int row = idx >> 3, c = idx & 7;
            const __half* sp = (tile == 0) ? Ah : (tile == 1) ? Al : Bh;
            long long grow = (long long)((tile < 2) ? m0 : n0) + row;
            const __half* src = sp + grow*K + k0 + c*8;
            uint32_t dst = sb + st*49152 + tile*16384 + row*128 + ((c ^ (row & 7)) << 4);
            CP_ASYNC16(dst, src);
        }
    };

    const int NS = K >> 6;
    ld_stage(0, 0);
    CP_COMMIT();
    for (int s = 0; s < NS; s++) {
        if (s + 1 < NS) { ld_stage((s + 1) & 1, (s + 1) << 6); CP_COMMIT(); CP_WAIT(1); }
        else            { CP_WAIT(0); }
        __syncthreads();
        uint32_t base = sb + (s & 1)*49152;
        #pragma unroll
        for (int ks = 0; ks < 4; ks++) {
            uint32_t ah[2][4], al[2][4];
            #pragma unroll
            for (int f = 0; f < 2; f++) {
                int row = wm*32 + f*16 + (lane & 15);
                int ch  = ks*2 + (lane >> 4);
                uint32_t off = row*128 + ((ch ^ (row & 7)) << 4);
                ldsm_x4(ah[f], base + off);
                ldsm_x4(al[f], base + 16384 + off);
            }
            uint32_t bh[4][4];
            #pragma unroll
            for (int g = 0; g < 4; g++) {
                int row = wn*64 + g*16 + (lane & 7) + ((lane & 16) >> 1);
                int ch  = ks*2 + ((lane >> 3) & 1);
                uint32_t off = row*128 + ((ch ^ (row & 7)) << 4);
                ldsm_x4(bh[g], base + 32768 + off);
            }
            #pragma unroll
            for (int f = 0; f < 2; f++)
                #pragma unroll
                for (int g = 0; g < 4; g++) {
                    mma16816(acc[f][2*g],   ah[f], &bh[g][0]);
                    mma16816(acc[f][2*g+1], ah[f], &bh[g][2]);
                    mma16816(acc[f][2*g],   al[f], &bh[g][0]);
                    mma16816(acc[f][2*g+1], al[f], &bh[g][2]);
                }
        }
        __syncthreads();
    }

    // epilogue
    const int lr = lane >> 2, lc = (lane & 3)*2;
    #pragma unroll
    for (int f = 0; f < 2; f++) {
        int r0 = m0 + wm*32 + f*16 + lr;
        #pragma unroll
        for (int nf = 0; nf < 8; nf++) {
            int col = n0 + wn*64 + nf*8 + lc;
            float c0 = acc[f][nf][0], c1 = acc[f][nf][1];
            float c2 = acc[f][nf][2], c3 = acc[f][nf][3];
            if (EPI == EPI_QKV) {
                int which = col >> 9, cq = col & 511;
                const float* bp = (which == 0) ? bias0 : (which == 1) ? bias1 : bias2;
                float2 bv = *(const float2*)(bp + cq);
                c0 += bv.x; c1 += bv.y; c2 += bv.x; c3 += bv.y;
                __half* dh = (which == 0) ? qh_ : (which == 1) ? kh_ : vh_;
                int hh = cq >> 6, hd = cq & 63;
                #pragma unroll
                for (int rr = 0; rr < 2; rr++) {
                    int r = r0 + rr*8;
                    int bb = r >> 11, srow = r & (S_-1);
                    long long o = (((long long)(bb*H_ + hh))*S_ + srow)*HD_ + hd;
                    uint32_t hi, lo;
                    if (rr == 0) split_pair(c0, c1, hi, lo);
                    else         split_pair(c2, c3, hi, lo);
                    *(uint32_t*)(dh + o) = hi;
                    if (which == 0) *(uint32_t*)(ql_ + o) = lo;  // only q needs lo
                }
            } else {
                float2 bv = *(const float2*)(bias0 + col);
                c0 += bv.x; c1 += bv.y; c2 += bv.x; c3 += bv.y;
                if (EPI == EPI_RESID) {
                    float2 r0v = *(const float2*)(resid + (long long)r0*N + col);
                    float2 r1v = *(const float2*)(resid + (long long)(r0+8)*N + col);
                    *(float2*)(Cf + (long long)r0*N + col)     = make_float2(c0 + r0v.x, c1 + r0v.y);
                    *(float2*)(Cf + (long long)(r0+8)*N + col) = make_float2(c2 + r1v.x, c3 + r1v.y);
                } else { // GELU -> fp16 hi/lo
                    c0 = 0.5f*c0*(1.0f + erff(c0*0.70710678118654752f));
                    c1 = 0.5f*c1*(1.0f + erff(c1*0.70710678118654752f));
                    c2 = 0.5f*c2*(1.0f + erff(c2*0.70710678118654752f));
                    c3 = 0.5f*c3*(1.0f + erff(c3*0.70710678118654752f));
                    uint32_t hi, lo;
                    split_pair(c0, c1, hi, lo);
                    *(uint32_t*)(Oh + (long long)r0*N + col) = hi;
                    *(uint32_t*)(Ol + (long long)r0*N + col) = lo;
                    split_pair(c2, c3, hi, lo);
                    *(uint32_t*)(Oh + (long long)(r0+8)*N + col) = hi;
                    *(uint32_t*)(Ol + (long long)(r0+8)*N + col) = lo;
                }
            }
        }
    }
}

// ======= HMMA flash attention: QK 2-product, PV 1-product, fp16 bias ========
#define ATT_SMEM (16384 + 2*16384)

__global__ __launch_bounds__(128) void attn_mma_kernel(
    const __half* __restrict__ Qh, const __half* __restrict__ Ql,
    const __half* __restrict__ Kh, const __half* __restrict__ Vh,
    const __half* __restrict__ bias,
    __half* __restrict__ Ohi, __half* __restrict__ Olo)
{
    extern __shared__ char smc[];
    const uint32_t sb = smem_u32(smc);
    const int t = threadIdx.x, lane = t & 31, w = t >> 5;
    const int q0 = blockIdx.x*64, hh = blockIdx.y, bb = blockIdx.z;
    const long long bhs = (long long)(bb*H_ + hh)*S_;
    const int lr = lane >> 2, lc = (lane & 3)*2;

    // Q prologue load (hi + lo tiles)
    #pragma unroll
    for (int i = 0; i < 8; i++) {
        int gid = t + i*128;
        int tile = gid >> 9, idx = gid & 511;
        int row = idx >> 3, c = idx & 7;
        const __half* sp = tile ? Ql : Qh;
        const __half* src = sp + (bhs + q0 + row)*HD_ + c*8;
        uint32_t dst = sb + tile*8192 + row*128 + ((c ^ (row & 7)) << 4);
        CP_ASYNC16(dst, src);
    }
    CP_COMMIT();

    auto ld_stage = [&](int st, int kt) {
        uint32_t base = sb + 16384 + st*16384;
        #pragma unroll
        for (int i = 0; i < 8; i++) {
            int gid = t + i*128;
            int tile = gid >> 9, idx = gid & 511;   // 0=Kh, 1=Vh
            int row = idx >> 3, c = idx & 7;
            const __half* sp = tile ? Vh : Kh;
            const __half* src = sp + (bhs + kt*64 + row)*HD_ + c*8;
            uint32_t dst = base + tile*8192 + row*128 + ((c ^ (row & 7)) << 4);
            CP_ASYNC16(dst, src);
        }
    };
    ld_stage(0, 0);
    CP_COMMIT();
    CP_WAIT(1);
    __syncthreads();

    // Q frags (persistent)
    uint32_t qfh[4][4], qfl[4][4];
    #pragma unroll
    for (int ks = 0; ks < 4; ks++) {
        int row = w*16 + (lane & 15);
        int ch  = ks*2 + (lane >> 4);
        uint32_t off = row*128 + ((ch ^ (row & 7)) << 4);
        ldsm_x4(qfh[ks], sb + off);
        ldsm_x4(qfl[ks], sb + 8192 + off);
    }

    float Oacc[8][4];
    #pragma unroll
    for (int nf = 0; nf < 8; nf++)
        #pragma unroll
        for (int j = 0; j < 4; j++) Oacc[nf][j] = 0.f;
    float ms0 = -3e38f, ms1 = -3e38f, ls0 = 0.f, ls1 = 0.f;

    const int NT = S_/64;
    for (int kt = 0; kt < NT; kt++) {
        if (kt + 1 < NT) { ld_stage((kt + 1) & 1, kt + 1); CP_COMMIT(); CP_WAIT(1); }
        else             { CP_WAIT(0); }
        __syncthreads();
        uint32_t base = sb + 16384 + (kt & 1)*16384;

        // S = Q @ K^T (Qh*Kh + Ql*Kh)
        float sacc[8][4];
        #pragma unroll
        for (int nf = 0; nf < 8; nf++)
            #pragma unroll
            for (int j = 0; j < 4; j++) sacc[nf][j] = 0.f;
        #pragma unroll
        for (int ks = 0; ks < 4; ks++) {
            uint32_t kh4[4][4];
            #pragma unroll
            for (int g = 0; g < 4; g++) {
                int row = g*16 + (lane & 7) + ((lane & 16) >> 1);
                int ch  = ks*2 + ((lane >> 3) & 1);
                uint32_t off = row*128 + ((ch ^ (row & 7)) << 4);
                ldsm_x4(kh4[g], base + off);
            }
            #pragma unroll
            for (int g = 0; g < 4; g++) {
                mma16816(sacc[2*g],   qfh[ks], &kh4[g][0]);
                mma16816(sacc[2*g+1], qfh[ks], &kh4[g][2]);
                mma16816(sacc[2*g],   qfl[ks], &kh4[g][0]);
                mma16816(sacc[2*g+1], qfl[ks], &kh4[g][2]);
            }
        }

        // fp16 bias + scale, row maxes
        int r0 = q0 + w*16 + lr;
        const __half* bp0 = bias + ((long long)bb*S_ + r0)*S_ + kt*64 + lc;
        const __half* bp1 = bp0 + 8*S_;
        float rm0 = -3e38f, rm1 = -3e38f;
        #pragma unroll
        for (int nf = 0; nf < 8; nf++) {
            float2 b0 = __half22float2(*(const __half2*)(bp0 + nf*8));
            float2 b1 = __half22float2(*(const __half2*)(bp1 + nf*8));
            sacc[nf][0] = sacc[nf][0]*0.125f + b0.x;
            sacc[nf][1] = sacc[nf][1]*0.125f + b0.y;
            sacc[nf][2] = sacc[nf][2]*0.125f + b1.x;
            sacc[nf][3] = sacc[nf][3]*0.125f + b1.y;
            rm0 = fmaxf(rm0, fmaxf(sacc[nf][0], sacc[nf][1]));
            rm1 = fmaxf(rm1, fmaxf(sacc[nf][2], sacc[nf][3]));
        }
        rm0 = fmaxf(rm0, __shfl_xor_sync(0xffffffffu, rm0, 1));
        rm0 = fmaxf(rm0, __shfl_xor_sync(0xffffffffu, rm0, 2));
        rm1 = fmaxf(rm1, __shfl_xor_sync(0xffffffffu, rm1, 1));
        rm1 = fmaxf(rm1, __shfl_xor_sync(0xffffffffu, rm1, 2));
        float mn0 = fmaxf(ms0, rm0), mn1 = fmaxf(ms1, rm1);
        float al0 = __expf(ms0 - mn0), al1 = __expf(ms1 - mn1);
        ms0 = mn0; ms1 = mn1;
        float rs0 = 0.f, rs1 = 0.f;
        #pragma unroll
        for (int nf = 0; nf < 8; nf++) {
            sacc[nf][0] = __expf(sacc[nf][0] - mn0);
            sacc[nf][1] = __expf(sacc[nf][1] - mn0);
            sacc[nf][2] = __expf(sacc[nf][2] - mn1);
            sacc[nf][3] = __expf(sacc[nf][3] - mn1);
            rs0 += sacc[nf][0] + sacc[nf][1];
            rs1 += sacc[nf][2] + sacc[nf][3];
        }
        rs0 += __shfl_xor_sync(0xffffffffu, rs0, 1);
        rs0 += __shfl_xor_sync(0xffffffffu, rs0, 2);
        rs1 += __shfl_xor_sync(0xffffffffu, rs1, 1);
        rs1 += __shfl_xor_sync(0xffffffffu, rs1, 2);
        ls0 = ls0*al0 + rs0;
        ls1 = ls1*al1 + rs1;
        #pragma unroll
        for (int nf = 0; nf < 8; nf++) {
            Oacc[nf][0] *= al0; Oacc[nf][1] *= al0;
            Oacc[nf][2] *= al1; Oacc[nf][3] *= al1;
        }

        // P -> fp16 hi frags (C-frag layout == A-frag layout)
        uint32_t ph[4][4];
        #pragma unroll
        for (int j = 0; j < 4; j++) {
            ph[j][0] = pack2(sacc[2*j][0],   sacc[2*j][1]);
            ph[j][1] = pack2(sacc[2*j][2],   sacc[2*j][3]);
            ph[j][2] = pack2(sacc[2*j+1][0], sacc[2*j+1][1]);
            ph[j][3] = pack2(sacc[2*j+1][2], sacc[2*j+1][3]);
        }

        // O += Ph @ Vh (1-product), V via trans ldmatrix
        #pragma unroll
        for (int j = 0; j < 4; j++) {
            uint32_t vh4[4][4];
            #pragma unroll
            for (int g = 0; g < 4; g++) {
                int row = j*16 + (lane & 7) + (lane & 8);
                int ch  = g*2 + ((lane >> 4) & 1);
                uint32_t off = row*128 + ((ch ^ (row & 7)) << 4);
                ldsm_x4_t(vh4[g], base + 8192 + off);
            }
            #pragma unroll
            for (int g = 0; g < 4; g++) {
                mma16816(Oacc[2*g],   ph[j], &vh4[g][0]);
                mma16816(Oacc[2*g+1], ph[j], &vh4[g][2]);
            }
        }
        __syncthreads();
    }

    // epilogue -> fp16 hi/lo into [B,S,D]
    float inv0 = 1.0f/ls0, inv1 = 1.0f/ls1;
    long long rowA = ((long long)bb*S_ + q0 + w*16 + lr)*D_ + hh*HD_;
    long long rowB = rowA + 8LL*D_;
    #pragma unroll
    for (int nf = 0; nf < 8; nf++) {
        int hd = nf*8 + lc;
        uint32_t hi, lo;
        split_pair(Oacc[nf][0]*inv0, Oacc[nf][1]*inv0, hi, lo);
        *(uint32_t*)(Ohi + rowA + hd) = hi;
        *(uint32_t*)(Olo + rowA + hd) = lo;
        split_pair(Oacc[nf][2]*inv1, Oacc[nf][3]*inv1, hi, lo);
        *(uint32_t*)(Ohi + rowB + hd) = hi;
        *(uint32_t*)(Olo + rowB + hd) = lo;
    }
}

// ---------------------------- launch ---------------------------------------
extern "C" void kernel_launch(void* const* d_in, const int* in_sizes, int n_in,
                              void* d_out, int out_size)
{
    const float* x    = (const float*)d_in[0];
    const int*   adj  = (const int*)  d_in[1];
    const float* edge = (const float*)d_in[2];
    const float* ln1g = (const float*)d_in[3];
    const float* ln1b = (const float*)d_in[4];
    const float* ln2g = (const float*)d_in[5];
    const float* ln2b = (const float*)d_in[6];
    const float* wq = (const float*)d_in[7];  const float* bq = (const float*)d_in[8];
    const float* wk = (const float*)d_in[9];  const float* bk = (const float*)d_in[10];
    const float* wv = (const float*)d_in[11]; const float* bv = (const float*)d_in[12];
    const float* wo = (const float*)d_in[13]; const float* bo = (const float*)d_in[14];
    const float* w1 = (const float*)d_in[15]; const float* b1 = (const float*)d_in[16];
    const float* w2 = (const float*)d_in[17]; const float* b2 = (const float*)d_in[18];
    float* out = (float*)d_out;

    float *x1;
    __half *biasc;
    cudaGetSymbolAddress((void**)&x1,    g_x1);
    cudaGetSymbolAddress((void**)&biasc, g_bias);
    __half *pah, *pal, *qah, *qal;
    __half *qh, *ql, *kh, *vh;
    __half *wqkvh, *woh, *w1h, *w2h;
    cudaGetSymbolAddress((void**)&pah, g_pa_hi); cudaGetSymbolAddress((void**)&pal, g_pa_lo);
    cudaGetSymbolAddress((void**)&qah, g_qa_hi); cudaGetSymbolAddress((void**)&qal, g_qa_lo);
    cudaGetSymbolAddress((void**)&qh, g_qh); cudaGetSymbolAddress((void**)&ql, g_ql);
    cudaGetSymbolAddress((void**)&kh, g_kh); cudaGetSymbolAddress((void**)&vh, g_vh);
    cudaGetSymbolAddress((void**)&wqkvh, g_wqkv_hi);
    cudaGetSymbolAddress((void**)&woh, g_wo_hi);
    cudaGetSymbolAddress((void**)&w1h, g_w1_hi);
    cudaGetSymbolAddress((void**)&w2h, g_w2_hi);

    cudaFuncSetAttribute(mma_gemm<EPI_QKV>,
        cudaFuncAttributeMaxDynamicSharedMemorySize, GEMM_SMEM);
    cudaFuncSetAttribute(mma_gemm<EPI_RESID>,
        cudaFuncAttributeMaxDynamicSharedMemorySize, GEMM_SMEM);
    cudaFuncSetAttribute(mma_gemm<EPI_GELU>,
        cudaFuncAttributeMaxDynamicSharedMemorySize, GEMM_SMEM);
    cudaFuncSetAttribute(attn_mma_kernel,
        cudaFuncAttributeMaxDynamicSharedMemorySize, ATT_SMEM);

    // side stream + events, created once (outside graph capture on first call)
    static cudaStream_t s1 = nullptr;
    static cudaEvent_t evFork = nullptr, evJoin = nullptr;
    if (!s1) {
        cudaStreamCreateWithFlags(&s1, cudaStreamNonBlocking);
        cudaEventCreateWithFlags(&evFork, cudaEventDisableTiming);
        cudaEventCreateWithFlags(&evJoin, cudaEventDisableTiming);
    }

    // fork: side stream does bias + wo/w1/w2 conversions
    cudaEventRecord(evFork, 0);
    cudaStreamWaitEvent(s1, evFork, 0);
    bias_kernel<<<(B_*S_*S_/4)/256, 256, 0, s1>>>(
        (const int4*)adj, (const float4*)edge, (uint2*)biasc);
    dim3 wb(256);
    wconvT_kernel<<<dim3(16,16), wb, 0, s1>>>(wo, woh, D_, D_);
    wconvT_kernel<<<dim3(64,16), wb, 0, s1>>>(w1, w1h, D_, DFF);
    wconvT_kernel<<<dim3(16,64), wb, 0, s1>>>(w2, w2h, DFF, D_);
    cudaEventRecord(evJoin, s1);

    // main: qkv weight conversions + LN1 + QKV gemm
    wconvT_kernel<<<dim3(16,16), wb>>>(wq, wqkvh,           D_, D_);
    wconvT_kernel<<<dim3(16,16), wb>>>(wk, wqkvh + D_*D_,   D_, D_);
    wconvT_kernel<<<dim3(16,16), wb>>>(wv, wqkvh + 2*D_*D_, D_, D_);
    ln_f16_kernel<<<MTOK, 256>>>(x, ln1g, ln1b, pah, pal);
    mma_gemm<EPI_QKV><<<dim3(12, 32), 256, GEMM_SMEM>>>(
        pah, pal, wqkvh, bq, bk, bv, nullptr, nullptr,
        nullptr, nullptr, qh, ql, kh, vh, MTOK, 3*D_, D_);

    // join, then attention
    cudaStreamWaitEvent(0, evJoin, 0);
    attn_mma_kernel<<<dim3(S_/64, H_, B_), 128, ATT_SMEM>>>(
        qh, ql, kh, vh, biasc, pah, pal);

    // O projection + residual -> x1 (fp32)
    mma_gemm<EPI_RESID><<<dim3(4, 32), 256, GEMM_SMEM>>>(
        pah, pal, woh, bo, nullptr, nullptr, x, x1,
        nullptr, nullptr, nullptr, nullptr, nullptr, nullptr, MTOK, D_, D_);

    // LN2 -> fp16 split
    ln_f16_kernel<<<MTOK, 256>>>(x1, ln2g, ln2b, pah, pal);

    // MLP up + exact GELU -> fp16 split
    mma_gemm<EPI_GELU><<<dim3(16, 32), 256, GEMM_SMEM>>>(
        pah, pal, w1h, b1, nullptr, nullptr, nullptr, nullptr,
        qah, qal, nullptr, nullptr, nullptr, nullptr, MTOK, DFF, D_);

    // MLP down + residual -> out
    mma_gemm<EPI_RESID><<<dim3(4, 32), 256, GEMM_SMEM>>>(
        qah, qal, w2h, b2, nullptr, nullptr, x1, out,
        nullptr, nullptr, nullptr, nullptr, nullptr, nullptr, MTOK, D_, DFF);
}

// round 6
// speedup vs baseline: 6.0222x; 1.1935x over previous
#include <cuda_runtime.h>
#include <cuda_fp16.h>
#include <math.h>
#include <cstdint>

#define B_   2
#define S_   2048
#define D_   512
#define H_   8
#define HD_  64
#define MTOK (B_*S_)      // 4096
#define DFF  (4*D_)       // 2048

// ---------------- scratch (device globals; no allocation allowed) ----------
__device__ float  g_x1  [MTOK*D_];
__device__ __half g_bias[(long long)B_*S_*S_];         // combined mask+edge bias (fp16)

// fp16 activation buffers
__device__ __half g_pa_hi[MTOK*D_];             // nx / att / n2
__device__ __half g_pa_lo[MTOK*D_];
__device__ __half g_qa_hi[MTOK*DFF];            // mlp hidden (hi only)

// q hi/lo, k/v hi-only, [B,H,S,HD]
__device__ __half g_qh[MTOK*D_], g_ql[MTOK*D_];
__device__ __half g_kh[MTOK*D_];
__device__ __half g_vh[MTOK*D_];

// fp16 transposed weights [N][K], hi-only
__device__ __half g_wqkv_hi[3*D_*D_];
__device__ __half g_wo_hi[D_*D_];
__device__ __half g_w1_hi[DFF*D_];
__device__ __half g_w2_hi[D_*DFF];

// ======================= PTX helpers ========================================
__device__ __forceinline__ uint32_t smem_u32(const void* p) {
    uint32_t a;
    asm("{ .reg .u64 t; cvta.to.shared.u64 t, %1; cvt.u32.u64 %0, t; }"
        : "=r"(a) : "l"(p));
    return a;
}
#define CP_ASYNC16(dst, src) \
    asm volatile("cp.async.cg.shared.global [%0], [%1], 16;" :: "r"(dst), "l"(src))
#define CP_COMMIT() asm volatile("cp.async.commit_group;" ::: "memory")
#define CP_WAIT(n)  asm volatile("cp.async.wait_group %0;" :: "n"(n) : "memory")

__device__ __forceinline__ void ldsm_x4(uint32_t* r, uint32_t a) {
    asm volatile("ldmatrix.sync.aligned.m8n8.x4.shared.b16 {%0,%1,%2,%3}, [%4];"
        : "=r"(r[0]), "=r"(r[1]), "=r"(r[2]), "=r"(r[3]) : "r"(a));
}
__device__ __forceinline__ void ldsm_x4_t(uint32_t* r, uint32_t a) {
    asm volatile("ldmatrix.sync.aligned.m8n8.x4.trans.shared.b16 {%0,%1,%2,%3}, [%4];"
        : "=r"(r[0]), "=r"(r[1]), "=r"(r[2]), "=r"(r[3]) : "r"(a));
}
__device__ __forceinline__ void mma16816(float* c, const uint32_t* a, const uint32_t* b) {
    asm volatile("mma.sync.aligned.m16n8k16.row.col.f32.f16.f16.f32 "
        "{%0,%1,%2,%3}, {%4,%5,%6,%7}, {%8,%9}, {%0,%1,%2,%3};"
        : "+f"(c[0]), "+f"(c[1]), "+f"(c[2]), "+f"(c[3])
        : "r"(a[0]), "r"(a[1]), "r"(a[2]), "r"(a[3]), "r"(b[0]), "r"(b[1]));
}
__device__ __forceinline__ uint32_t packh(__half a, __half b) {
    return ((uint32_t)*(uint16_t*)&a) | ((uint32_t)*(uint16_t*)&b << 16);
}
__device__ __forceinline__ uint32_t pack2(float a, float b) {
    return packh(__float2half_rn(a), __float2half_rn(b));
}
__device__ __forceinline__ void split_pair(float a, float b, uint32_t& hi, uint32_t& lo) {
    __half ha = __float2half_rn(a), hb = __float2half_rn(b);
    __half la = __float2half_rn(a - __half2float(ha));
    __half lb = __float2half_rn(b - __half2float(hb));
    hi = packh(ha, hb);
    lo = packh(la, lb);
}

// ---------------- bias precompute: adj/edge -> combined fp16 ----------------
__global__ __launch_bounds__(256) void bias_kernel(
    const int4* __restrict__ adj, const float4* __restrict__ edge,
    uint2* __restrict__ out)
{
    int i = blockIdx.x*256 + threadIdx.x;
    int4 a = adj[i]; float4 e = edge[i];
    uint2 o;
    o.x = pack2(a.x ? 0.1f*e.x : -60000.f, a.y ? 0.1f*e.y : -60000.f);
    o.y = pack2(a.z ? 0.1f*e.z : -60000.f, a.w ? 0.1f*e.w : -60000.f);
    out[i] = o;
}

// ---------------- LayerNorm -> fp16 hi (+optional lo) -----------------------
__global__ __launch_bounds__(256) void ln_f16_kernel(
    const float* __restrict__ x, const float* __restrict__ g,
    const float* __restrict__ b, __half* __restrict__ ohi,
    __half* __restrict__ olo)
{
    int row = blockIdx.x;
    const float2 v = ((const float2*)(x + (long long)row*D_))[threadIdx.x];
    float s  = v.x + v.y;
    float ss = v.x*v.x + v.y*v.y;
    #pragma unroll
    for (int o = 16; o; o >>= 1) {
        s  += __shfl_xor_sync(0xffffffffu, s,  o);
        ss += __shfl_xor_sync(0xffffffffu, ss, o);
    }
    __shared__ float sm_s[8], sm_ss[8];
    int w = threadIdx.x >> 5, l = threadIdx.x & 31;
    if (l == 0) { sm_s[w] = s; sm_ss[w] = ss; }
    __syncthreads();
    float ts = 0.f, tss = 0.f;
    #pragma unroll
    for (int i = 0; i < 8; i++) { ts += sm_s[i]; tss += sm_ss[i]; }
    float mu  = ts * (1.0f/D_);
    float var = tss * (1.0f/D_) - mu*mu;
    float inv = rsqrtf(var + 1e-5f);
    float2 gg = ((const float2*)g)[threadIdx.x];
    float2 bb = ((const float2*)b)[threadIdx.x];
    float ox = (v.x - mu)*inv*gg.x + bb.x;
    float oy = (v.y - mu)*inv*gg.y + bb.y;
    uint32_t hi, lo;
    split_pair(ox, oy, hi, lo);
    *(uint32_t*)(ohi + (long long)row*D_ + threadIdx.x*2) = hi;
    if (olo)
        *(uint32_t*)(olo + (long long)row*D_ + threadIdx.x*2) = lo;
}

// ---------------- weight transpose: W[K,N] -> T[N,K] fp16 hi ---------------
__global__ __launch_bounds__(256) void wconvT_kernel(
    const float* __restrict__ W, __half* __restrict__ Thi, int K, int N)
{
    __shared__ float t[32][33];
    int tx = threadIdx.x & 31, ty = threadIdx.x >> 5;
    int k0 = blockIdx.y*32, n0 = blockIdx.x*32;
    #pragma unroll
    for (int i = 0; i < 4; i++)
        t[ty + i*8][tx] = W[(long long)(k0 + ty + i*8)*N + n0 + tx];
    __syncthreads();
    #pragma unroll
    for (int i = 0; i < 4; i++) {
        int n = n0 + ty + i*8, k = k0 + tx;
        Thi[(long long)n*K + k] = __float2half_rn(t[tx][ty + i*8]);
    }
}

// merged q/k/v weight transpose (grid.z selects which)
__global__ __launch_bounds__(256) void wconvT3_kernel(
    const float* __restrict__ Wq, const float* __restrict__ Wk,
    const float* __restrict__ Wv, __half* __restrict__ Tbase)
{
    const float* W = (blockIdx.z == 0) ? Wq : (blockIdx.z == 1) ? Wk : Wv;
    __half* Thi = Tbase + (long long)blockIdx.z * D_ * D_;
    __shared__ float t[32][33];
    int tx = threadIdx.x & 31, ty = threadIdx.x >> 5;
    int k0 = blockIdx.y*32, n0 = blockIdx.x*32;
    #pragma unroll
    for (int i = 0; i < 4; i++)
        t[ty + i*8][tx] = W[(long long)(k0 + ty + i*8)*D_ + n0 + tx];
    __syncthreads();
    #pragma unroll
    for (int i = 0; i < 4; i++) {
        int n = n0 + ty + i*8, k = k0 + tx;
        Thi[(long long)n*D_ + k] = __float2half_rn(t[tx][ty + i*8]);
    }
}

// ============== HMMA fp16 GEMM: 128x128 blocks, 1 or 2 products ============
// C = (Ah[+Al])[M,K] @ Bh[N,K]^T ; fp32 accum.
#define EPI_QKV   1
#define EPI_RESID 2
#define EPI_GELU  3
#define GEMM_SMEM_2 98304   // 2 stages x (3 tiles x 16KB)
#define GEMM_SMEM_1 65536   // 2 stages x (2 tiles x 16KB)

template<int EPI, bool TWO>
__global__ __launch_bounds__(256) void mma_gemm(
    const __half* __restrict__ Ah, const __half* __restrict__ Al,
    const __half* __restrict__ Bh,
    const float* __restrict__ bias0, const float* __restrict__ bias1,
    const float* __restrict__ bias2, const float* __restrict__ resid,
    float* __restrict__ Cf,
    __half* __restrict__ Oh, __half* __restrict__ Ol,
    __half* __restrict__ qh_, __half* __restrict__ ql_,
    __half* __restrict__ kh_, __half* __restrict__ vh_,
    int M, int N, int K)
{
    constexpr int TILES = TWO ? 3 : 2;
    constexpr int STG   = TILES * 16384;
    constexpr int BOFF  = (TILES - 1) * 16384;
    extern __shared__ char smc[];
    const uint32_t sb = smem_u32(smc);
    const int t = threadIdx.x, lane = t & 31;
    const int wid = t >> 5, wm = wid & 3, wn = wid >> 2;
    const int m0 = blockIdx.y*128, n0 = blockIdx.x*128;

    float acc[2][8][4];
    #pragma unroll
    for (int f = 0; f < 2; f++)
        #pragma unroll
        for (int nf = 0; nf < 8; nf++)
            #pragma unroll
            for (int j = 0; j < 4; j++) acc[f][nf][j] = 0.f;

    auto ld_stage = [&](int st, int k0) {
        #pragma unroll
        for (int i = 0; i < 4*TILES; i++) {
            int gid = t + i*256;
            int tile = gid >> 10, idx = gid & 1023;
            int row = idx >> 3, c = idx & 7;
            const __half* sp;
            long long rb;
            if (TWO) {
                sp = (tile == 0) ? Ah : (tile == 1) ? Al : Bh;
                rb = (tile < 2) ? m0 : n0;
            } else {
                sp = (tile == 0) ? Ah : Bh;
                rb = (tile == 0) ? m0 : n0;
            }
            const __half* src = sp + (rb + row)*(long long)K + k0 + c*8;
            uint32_t dst = sb + st*STG + tile*16384 + row*128 + ((c ^ (row & 7)) << 4);
            CP_ASYNC16(dst, src);
        }
    };

    const int NS = K >> 6;
    ld_stage(0, 0);
    CP_COMMIT();
    for (int s = 0; s < NS; s++) {
        if (s + 1 < NS) { ld_stage((s + 1) & 1, (s + 1) << 6); CP_COMMIT(); CP_WAIT(1); }
        else            { CP_WAIT(0); }
        __syncthreads();
        uint32_t base = sb + (s & 1)*STG;
        #pragma unroll
        for (int ks = 0; ks < 4; ks++) {
            uint32_t ah[2][4], al[2][4];
            #pragma unroll
            for (int f = 0; f < 2; f++) {
                int row = wm*32 + f*16 + (lane & 15);
                int ch  = ks*2 + (lane >> 4);
                uint32_t off = row*128 + ((ch ^ (row & 7)) << 4);
                ldsm_x4(ah[f], base + off);
                if (TWO) ldsm_x4(al[f], base + 16384 + off);
            }
            uint32_t bh[4][4];
            #pragma unroll
            for (int g = 0; g < 4; g++) {
                int row = wn*64 + g*16 + (lane & 7) + ((lane & 16) >> 1);
                int ch  = ks*2 + ((lane >> 3) & 1);
                uint32_t off = row*128 + ((ch ^ (row & 7)) << 4);
                ldsm_x4(bh[g], base + BOFF + off);
            }
            #pragma unroll
            for (int f = 0; f < 2; f++)
                #pragma unroll
                for (int g = 0; g < 4; g++) {
                    mma16816(acc[f][2*g],   ah[f], &bh[g][0]);
                    mma16816(acc[f][2*g+1], ah[f], &bh[g][2]);
                    if (TWO) {
                        mma16816(acc[f][2*g],   al[f], &bh[g][0]);
                        mma16816(acc[f][2*g+1], al[f], &bh[g][2]);
                    }
                }
        }
        __syncthreads();
    }

    // epilogue
    const int lr = lane >> 2, lc = (lane & 3)*2;
    #pragma unroll
    for (int f = 0; f < 2; f++) {
        int r0 = m0 + wm*32 + f*16 + lr;
        #pragma unroll
        for (int nf = 0; nf < 8; nf++) {
            int col = n0 + wn*64 + nf*8 + lc;
            float c0 = acc[f][nf][0], c1 = acc[f][nf][1];
            float c2 = acc[f][nf][2], c3 = acc[f][nf][3];
            if (EPI == EPI_QKV) {
                int which = col >> 9, cq = col & 511;
                const float* bp = (which == 0) ? bias0 : (which == 1) ? bias1 : bias2;
                float2 bv = *(const float2*)(bp + cq);
                c0 += bv.x; c1 += bv.y; c2 += bv.x; c3 += bv.y;
                __half* dh = (which == 0) ? qh_ : (which == 1) ? kh_ : vh_;
                int hh = cq >> 6, hd = cq & 63;
                #pragma unroll
                for (int rr = 0; rr < 2; rr++) {
                    int r = r0 + rr*8;
                    int bb = r >> 11, srow = r & (S_-1);
                    long long o = (((long long)(bb*H_ + hh))*S_ + srow)*HD_ + hd;
                    uint32_t hi, lo;
                    if (rr == 0) split_pair(c0, c1, hi, lo);
                    else         split_pair(c2, c3, hi, lo);
                    *(uint32_t*)(dh + o) = hi;
                    if (which == 0) *(uint32_t*)(ql_ + o) = lo;  // only q needs lo
                }
            } else {
                float2 bv = *(const float2*)(bias0 + col);
                c0 += bv.x; c1 += bv.y; c2 += bv.x; c3 += bv.y;
                if (EPI == EPI_RESID) {
                    float2 r0v = *(const float2*)(resid + (long long)r0*N + col);
                    float2 r1v = *(const float2*)(resid + (long long)(r0+8)*N + col);
                    *(float2*)(Cf + (long long)r0*N + col)     = make_float2(c0 + r0v.x, c1 + r0v.y);
                    *(float2*)(Cf + (long long)(r0+8)*N + col) = make_float2(c2 + r1v.x, c3 + r1v.y);
                } else { // GELU -> fp16 hi (lo optional)
                    c0 = 0.5f*c0*(1.0f + erff(c0*0.70710678118654752f));
                    c1 = 0.5f*c1*(1.0f + erff(c1*0.70710678118654752f));
                    c2 = 0.5f*c2*(1.0f + erff(c2*0.70710678118654752f));
                    c3 = 0.5f*c3*(1.0f + erff(c3*0.70710678118654752f));
                    *(uint32_t*)(Oh + (long long)r0*N + col)     = pack2(c0, c1);
                    *(uint32_t*)(Oh + (long long)(r0+8)*N + col) = pack2(c2, c3);
                }
            }
        }
    }
}

// ======= HMMA flash attention: 128-row Q tiles, QK 2-prod, PV 1-prod ========
#define ATT_SMEM 65536   // Q hi/lo 32KB + 2 stages x (K 8KB + V 8KB)

__global__ __launch_bounds__(256) void attn_mma_kernel(
    const __half* __restrict__ Qh, const __half* __restrict__ Ql,
    const __half* __restrict__ Kh, const __half* __restrict__ Vh,
    const __half* __restrict__ bias,
    __half* __restrict__ Ohi, __half* __restrict__ Olo)
{
    extern __shared__ char smc[];
    const uint32_t sb = smem_u32(smc);
    const int t = threadIdx.x, lane = t & 31, w = t >> 5;   // 8 warps
    const int q0 = blockIdx.x*128, hh = blockIdx.y, bb = blockIdx.z;
    const long long bhs = (long long)(bb*H_ + hh)*S_;
    const int lr = lane >> 2, lc = (lane & 3)*2;

    // Q prologue load (hi + lo, 128 rows each)
    #pragma unroll
    for (int i = 0; i < 8; i++) {
        int gid = t + i*256;
        int tile = gid >> 10, idx = gid & 1023;
        int row = idx >> 3, c = idx & 7;
        const __half* sp = tile ? Ql : Qh;
        const __half* src = sp + (bhs + q0 + row)*HD_ + c*8;
        uint32_t dst = sb + tile*16384 + row*128 + ((c ^ (row & 7)) << 4);
        CP_ASYNC16(dst, src);
    }
    CP_COMMIT();

    auto ld_stage = [&](int st, int kt) {
        uint32_t base = sb + 32768 + st*16384;
        #pragma unroll
        for (int i = 0; i < 4; i++) {
            int gid = t + i*256;
            int tile = gid >> 9, idx = gid & 511;   // 0=Kh, 1=Vh
            int row = idx >> 3, c = idx & 7;
            const __half* sp = tile ? Vh : Kh;
            const __half* src = sp + (bhs + kt*64 + row)*HD_ + c*8;
            uint32_t dst = base + tile*8192 + row*128 + ((c ^ (row & 7)) << 4);
            CP_ASYNC16(dst, src);
        }
    };
    ld_stage(0, 0);
    CP_COMMIT();
    CP_WAIT(1);
    __syncthreads();

    // Q frags (persistent): each warp owns 16 q-rows
    uint32_t qfh[4][4], qfl[4][4];
    #pragma unroll
    for (int ks = 0; ks < 4; ks++) {
        int row = w*16 + (lane & 15);
        int ch  = ks*2 + (lane >> 4);
        uint32_t off = row*128 + ((ch ^ (row & 7)) << 4);
        ldsm_x4(qfh[ks], sb + off);
        ldsm_x4(qfl[ks], sb + 16384 + off);
    }

    float Oacc[8][4];
    #pragma unroll
    for (int nf = 0; nf < 8; nf++)
        #pragma unroll
        for (int j = 0; j < 4; j++) Oacc[nf][j] = 0.f;
    float ms0 = -3e38f, ms1 = -3e38f, ls0 = 0.f, ls1 = 0.f;

    const int NT = S_/64;
    for (int kt = 0; kt < NT; kt++) {
        if (kt + 1 < NT) { ld_stage((kt + 1) & 1, kt + 1); CP_COMMIT(); CP_WAIT(1); }
        else             { CP_WAIT(0); }
        __syncthreads();
        uint32_t base = sb + 32768 + (kt & 1)*16384;

        // S = Q @ K^T (Qh*Kh + Ql*Kh)
        float sacc[8][4];
        #pragma unroll
        for (int nf = 0; nf < 8; nf++)
            #pragma unroll
            for (int j = 0; j < 4; j++) sacc[nf][j] = 0.f;
        #pragma unroll
        for (int ks = 0; ks < 4; ks++) {
            uint32_t kh4[4][4];
            #pragma unroll
            for (int g = 0; g < 4; g++) {
                int row = g*16 + (lane & 7) + ((lane & 16) >> 1);
                int ch  = ks*2 + ((lane >> 3) & 1);
                uint32_t off = row*128 + ((ch ^ (row & 7)) << 4);
                ldsm_x4(kh4[g], base + off);
            }
            #pragma unroll
            for (int g = 0; g < 4; g++) {
                mma16816(sacc[2*g],   qfh[ks], &kh4[g][0]);
                mma16816(sacc[2*g+1], qfh[ks], &kh4[g][2]);
                mma16816(sacc[2*g],   qfl[ks], &kh4[g][0]);
                mma16816(sacc[2*g+1], qfl[ks], &kh4[g][2]);
            }
        }

        // fp16 bias + scale, row maxes
        int r0 = q0 + w*16 + lr;
        const __half* bp0 = bias + ((long long)bb*S_ + r0)*S_ + kt*64 + lc;
        const __half* bp1 = bp0 + 8*S_;
        float rm0 = -3e38f, rm1 = -3e38f;
        #pragma unroll
        for (int nf = 0; nf < 8; nf++) {
            float2 b0 = __half22float2(*(const __half2*)(bp0 + nf*8));
            float2 b1 = __half22float2(*(const __half2*)(bp1 + nf*8));
            sacc[nf][0] = sacc[nf][0]*0.125f + b0.x;
            sacc[nf][1] = sacc[nf][1]*0.125f + b0.y;
            sacc[nf][2] = sacc[nf][2]*0.125f + b1.x;
            sacc[nf][3] = sacc[nf][3]*0.125f + b1.y;
            rm0 = fmaxf(rm0, fmaxf(sacc[nf][0], sacc[nf][1]));
            rm1 = fmaxf(rm1, fmaxf(sacc[nf][2], sacc[nf][3]));
        }
        rm0 = fmaxf(rm0, __shfl_xor_sync(0xffffffffu, rm0, 1));
        rm0 = fmaxf(rm0, __shfl_xor_sync(0xffffffffu, rm0, 2));
        rm1 = fmaxf(rm1, __shfl_xor_sync(0xffffffffu, rm1, 1));
        rm1 = fmaxf(rm1, __shfl_xor_sync(0xffffffffu, rm1, 2));
        float mn0 = fmaxf(ms0, rm0), mn1 = fmaxf(ms1, rm1);
        float al0 = __expf(ms0 - mn0), al1 = __expf(ms1 - mn1);
        ms0 = mn0; ms1 = mn1;
        float rs0 = 0.f, rs1 = 0.f;
        #pragma unroll
        for (int nf = 0; nf < 8; nf++) {
            sacc[nf][0] = __expf(sacc[nf][0] - mn0);
            sacc[nf][1] = __expf(sacc[nf][1] - mn0);
            sacc[nf][2] = __expf(sacc[nf][2] - mn1);
            sacc[nf][3] = __expf(sacc[nf][3] - mn1);
            rs0 += sacc[nf][0] + sacc[nf][1];
            rs1 += sacc[nf][2] + sacc[nf][3];
        }
        rs0 += __shfl_xor_sync(0xffffffffu, rs0, 1);
        rs0 += __shfl_xor_sync(0xffffffffu, rs0, 2);
        rs1 += __shfl_xor_sync(0xffffffffu, rs1, 1);
        rs1 += __shfl_xor_sync(0xffffffffu, rs1, 2);
        ls0 = ls0*al0 + rs0;
        ls1 = ls1*al1 + rs1;
        #pragma unroll
        for (int nf = 0; nf < 8; nf++) {
            Oacc[nf][0] *= al0; Oacc[nf][1] *= al0;
            Oacc[nf][2] *= al1; Oacc[nf][3] *= al1;
        }

        // P -> fp16 hi frags (C-frag layout == A-frag layout)
        uint32_t ph[4][4];
        #pragma unroll
        for (int j = 0; j < 4; j++) {
            ph[j][0] = pack2(sacc[2*j][0],   sacc[2*j][1]);
            ph[j][1] = pack2(sacc[2*j][2],   sacc[2*j][3]);
            ph[j][2] = pack2(sacc[2*j+1][0], sacc[2*j+1][1]);
            ph[j][3] = pack2(sacc[2*j+1][2], sacc[2*j+1][3]);
        }

        // O += Ph @ Vh (1-product), V via trans ldmatrix
        #pragma unroll
        for (int j = 0; j < 4; j++) {
            uint32_t vh4[4][4];
            #pragma unroll
            for (int g = 0; g < 4; g++) {
                int row = j*16 + (lane & 7) + (lane & 8);
                int ch  = g*2 + ((lane >> 4) & 1);
                uint32_t off = row*128 + ((ch ^ (row & 7)) << 4);
                ldsm_x4_t(vh4[g], base + 8192 + off);
            }
            #pragma unroll
            for (int g = 0; g < 4; g++) {
                mma16816(Oacc[2*g],   ph[j], &vh4[g][0]);
                mma16816(Oacc[2*g+1], ph[j], &vh4[g][2]);
            }
        }
        __syncthreads();
    }

    // epilogue -> fp16 hi/lo into [B,S,D]
    float inv0 = 1.0f/ls0, inv1 = 1.0f/ls1;
    long long rowA = ((long long)bb*S_ + q0 + w*16 + lr)*D_ + hh*HD_;
    long long rowB = rowA + 8LL*D_;
    #pragma unroll
    for (int nf = 0; nf < 8; nf++) {
        int hd = nf*8 + lc;
        uint32_t hi, lo;
        split_pair(Oacc[nf][0]*inv0, Oacc[nf][1]*inv0, hi, lo);
        *(uint32_t*)(Ohi + rowA + hd) = hi;
        *(uint32_t*)(Olo + rowA + hd) = lo;
        split_pair(Oacc[nf][2]*inv1, Oacc[nf][3]*inv1, hi, lo);
        *(uint32_t*)(Ohi + rowB + hd) = hi;
        *(uint32_t*)(Olo + rowB + hd) = lo;
    }
}

// ---------------------------- launch ---------------------------------------
extern "C" void kernel_launch(void* const* d_in, const int* in_sizes, int n_in,
                              void* d_out, int out_size)
{
    const float* x    = (const float*)d_in[0];
    const int*   adj  = (const int*)  d_in[1];
    const float* edge = (const float*)d_in[2];
    const float* ln1g = (const float*)d_in[3];
    const float* ln1b = (const float*)d_in[4];
    const float* ln2g = (const float*)d_in[5];
    const float* ln2b = (const float*)d_in[6];
    const float* wq = (const float*)d_in[7];  const float* bq = (const float*)d_in[8];
    const float* wk = (const float*)d_in[9];  const float* bk = (const float*)d_in[10];
    const float* wv = (const float*)d_in[11]; const float* bv = (const float*)d_in[12];
    const float* wo = (const float*)d_in[13]; const float* bo = (const float*)d_in[14];
    const float* w1 = (const float*)d_in[15]; const float* b1 = (const float*)d_in[16];
    const float* w2 = (const float*)d_in[17]; const float* b2 = (const float*)d_in[18];
    float* out = (float*)d_out;

    float *x1;
    __half *biasc;
    cudaGetSymbolAddress((void**)&x1,    g_x1);
    cudaGetSymbolAddress((void**)&biasc, g_bias);
    __half *pah, *pal, *qah;
    __half *qh, *ql, *kh, *vh;
    __half *wqkvh, *woh, *w1h, *w2h;
    cudaGetSymbolAddress((void**)&pah, g_pa_hi); cudaGetSymbolAddress((void**)&pal, g_pa_lo);
    cudaGetSymbolAddress((void**)&qah, g_qa_hi);
    cudaGetSymbolAddress((void**)&qh, g_qh); cudaGetSymbolAddress((void**)&ql, g_ql);
    cudaGetSymbolAddress((void**)&kh, g_kh); cudaGetSymbolAddress((void**)&vh, g_vh);
    cudaGetSymbolAddress((void**)&wqkvh, g_wqkv_hi);
    cudaGetSymbolAddress((void**)&woh, g_wo_hi);
    cudaGetSymbolAddress((void**)&w1h, g_w1_hi);
    cudaGetSymbolAddress((void**)&w2h, g_w2_hi);

    cudaFuncSetAttribute((const void*)mma_gemm<EPI_QKV, true>,
        cudaFuncAttributeMaxDynamicSharedMemorySize, GEMM_SMEM_2);
    cudaFuncSetAttribute((const void*)mma_gemm<EPI_RESID, true>,
        cudaFuncAttributeMaxDynamicSharedMemorySize, GEMM_SMEM_2);
    cudaFuncSetAttribute((const void*)mma_gemm<EPI_GELU, false>,
        cudaFuncAttributeMaxDynamicSharedMemorySize, GEMM_SMEM_1);
    cudaFuncSetAttribute((const void*)mma_gemm<EPI_RESID, false>,
        cudaFuncAttributeMaxDynamicSharedMemorySize, GEMM_SMEM_1);
    cudaFuncSetAttribute(attn_mma_kernel,
        cudaFuncAttributeMaxDynamicSharedMemorySize, ATT_SMEM);

    // side stream + events, created once (outside graph capture on first call)
    static cudaStream_t s1 = nullptr;
    static cudaEvent_t evFork = nullptr, evJoin = nullptr;
    if (!s1) {
        cudaStreamCreateWithFlags(&s1, cudaStreamNonBlocking);
        cudaEventCreateWithFlags(&evFork, cudaEventDisableTiming);
        cudaEventCreateWithFlags(&evJoin, cudaEventDisableTiming);
    }

    // fork: side stream does bias + wo/w1/w2 conversions
    cudaEventRecord(evFork, 0);
    cudaStreamWaitEvent(s1, evFork, 0);
    dim3 wb(256);
    bias_kernel<<<(B_*S_*S_/4)/256, 256, 0, s1>>>(
        (const int4*)adj, (const float4*)edge, (uint2*)biasc);
    wconvT_kernel<<<dim3(16,16), wb, 0, s1>>>(wo, woh, D_, D_);
    wconvT_kernel<<<dim3(64,16), wb, 0, s1>>>(w1, w1h, D_, DFF);
    wconvT_kernel<<<dim3(16,64), wb, 0, s1>>>(w2, w2h, DFF, D_);
    cudaEventRecord(evJoin, s1);

    // main: LN1 + merged qkv weight conversion + QKV gemm
    ln_f16_kernel<<<MTOK, 256>>>(x, ln1g, ln1b, pah, pal);
    wconvT3_kernel<<<dim3(16,16,3), wb>>>(wq, wk, wv, wqkvh);
    mma_gemm<EPI_QKV, true><<<dim3(12, 32), 256, GEMM_SMEM_2>>>(
        pah, pal, wqkvh, bq, bk, bv, nullptr, nullptr,
        nullptr, nullptr, qh, ql, kh, vh, MTOK, 3*D_, D_);

    // join, then attention (128-row Q tiles)
    cudaStreamWaitEvent(0, evJoin, 0);
    attn_mma_kernel<<<dim3(S_/128, H_, B_), 256, ATT_SMEM>>>(
        qh, ql, kh, vh, biasc, pah, pal);

    // O projection + residual -> x1 (fp32), 2-product
    mma_gemm<EPI_RESID, true><<<dim3(4, 32), 256, GEMM_SMEM_2>>>(
        pah, pal, woh, bo, nullptr, nullptr, x, x1,
        nullptr, nullptr, nullptr, nullptr, nullptr, nullptr, MTOK, D_, D_);

    // LN2 -> fp16 hi only (MLP1 is 1-product)
    ln_f16_kernel<<<MTOK, 256>>>(x1, ln2g, ln2b, pah, nullptr);

    // MLP up + exact GELU -> fp16 hi, 1-product
    mma_gemm<EPI_GELU, false><<<dim3(16, 32), 256, GEMM_SMEM_1>>>(
        pah, nullptr, w1h, b1, nullptr, nullptr, nullptr, nullptr,
        qah, nullptr, nullptr, nullptr, nullptr, nullptr, MTOK, DFF, D_);

    // MLP down + residual -> out, 1-product
    mma_gemm<EPI_RESID, false><<<dim3(4, 32), 256, GEMM_SMEM_1>>>(
        qah, nullptr, w2h, b2, nullptr, nullptr, x1, out,
        nullptr, nullptr, nullptr, nullptr, nullptr, nullptr, MTOK, D_, DFF);
}

// round 7
// speedup vs baseline: 6.5920x; 1.0946x over previous
#include <cuda_runtime.h>
#include <cuda_fp16.h>
#include <math.h>
#include <cstdint>

#define B_   2
#define S_   2048
#define D_   512
#define H_   8
#define HD_  64
#define MTOK (B_*S_)      // 4096
#define DFF  (4*D_)       // 2048

#define QSC  0.1803368801111f   // 0.125 * log2(e)
#define BSC  0.1442695040889f   // 0.1  * log2(e)
#define MASKV (-43281.0f)       // -30000 * log2(e), fits fp16

// ---------------- scratch (device globals; no allocation allowed) ----------
__device__ float  g_x1  [MTOK*D_];
__device__ __half g_bias[(long long)B_*S_*S_];   // mask+edge bias, pre-scaled by log2e

// fp16 activation buffers (hi-only now)
__device__ __half g_pa_hi[MTOK*D_];              // nx / att / n2
__device__ __half g_qa_hi[MTOK*DFF];             // mlp hidden

// q hi/lo (pre-scaled by QSC), k/v hi-only, [B,H,S,HD]
__device__ __half g_qh[MTOK*D_], g_ql[MTOK*D_];
__device__ __half g_kh[MTOK*D_];
__device__ __half g_vh[MTOK*D_];

// fp16 transposed weights [N][K]
__device__ __half g_wqkv_hi[3*D_*D_];
__device__ __half g_wo_hi[D_*D_];
__device__ __half g_w1_hi[DFF*D_];
__device__ __half g_w2_hi[D_*DFF];

// ======================= PTX helpers ========================================
__device__ __forceinline__ uint32_t smem_u32(const void* p) {
    uint32_t a;
    asm("{ .reg .u64 t; cvta.to.shared.u64 t, %1; cvt.u32.u64 %0, t; }"
        : "=r"(a) : "l"(p));
    return a;
}
#define CP_ASYNC16(dst, src) \
    asm volatile("cp.async.cg.shared.global [%0], [%1], 16;" :: "r"(dst), "l"(src))
#define CP_COMMIT() asm volatile("cp.async.commit_group;" ::: "memory")
#define CP_WAIT(n)  asm volatile("cp.async.wait_group %0;" :: "n"(n) : "memory")

__device__ __forceinline__ void ldsm_x4(uint32_t* r, uint32_t a) {
    asm volatile("ldmatrix.sync.aligned.m8n8.x4.shared.b16 {%0,%1,%2,%3}, [%4];"
        : "=r"(r[0]), "=r"(r[1]), "=r"(r[2]), "=r"(r[3]) : "r"(a));
}
__device__ __forceinline__ void ldsm_x4_t(uint32_t* r, uint32_t a) {
    asm volatile("ldmatrix.sync.aligned.m8n8.x4.trans.shared.b16 {%0,%1,%2,%3}, [%4];"
        : "=r"(r[0]), "=r"(r[1]), "=r"(r[2]), "=r"(r[3]) : "r"(a));
}
__device__ __forceinline__ void mma16816(float* c, const uint32_t* a, const uint32_t* b) {
    asm volatile("mma.sync.aligned.m16n8k16.row.col.f32.f16.f16.f32 "
        "{%0,%1,%2,%3}, {%4,%5,%6,%7}, {%8,%9}, {%0,%1,%2,%3};"
        : "+f"(c[0]), "+f"(c[1]), "+f"(c[2]), "+f"(c[3])
        : "r"(a[0]), "r"(a[1]), "r"(a[2]), "r"(a[3]), "r"(b[0]), "r"(b[1]));
}
__device__ __forceinline__ float ex2f(float x) {
    float y; asm("ex2.approx.f32 %0, %1;" : "=f"(y) : "f"(x)); return y;
}
__device__ __forceinline__ uint32_t packh(__half a, __half b) {
    return ((uint32_t)*(uint16_t*)&a) | ((uint32_t)*(uint16_t*)&b << 16);
}
__device__ __forceinline__ uint32_t pack2(float a, float b) {
    return packh(__float2half_rn(a), __float2half_rn(b));
}
__device__ __forceinline__ void split_pair(float a, float b, uint32_t& hi, uint32_t& lo) {
    __half ha = __float2half_rn(a), hb = __float2half_rn(b);
    __half la = __float2half_rn(a - __half2float(ha));
    __half lb = __float2half_rn(b - __half2float(hb));
    hi = packh(ha, hb);
    lo = packh(la, lb);
}

// ---------------- bias precompute: adj/edge -> fp16, pre-scaled by log2e ----
__global__ __launch_bounds__(256) void bias_kernel(
    const int4* __restrict__ adj, const float4* __restrict__ edge,
    uint2* __restrict__ out)
{
    int i = blockIdx.x*256 + threadIdx.x;
    int4 a = adj[i]; float4 e = edge[i];
    uint2 o;
    o.x = pack2(a.x ? BSC*e.x : MASKV, a.y ? BSC*e.y : MASKV);
    o.y = pack2(a.z ? BSC*e.z : MASKV, a.w ? BSC*e.w : MASKV);
    out[i] = o;
}

// ---------------- LayerNorm -> fp16 hi ---------------------------------------
__global__ __launch_bounds__(256) void ln_f16_kernel(
    const float* __restrict__ x, const float* __restrict__ g,
    const float* __restrict__ b, __half* __restrict__ ohi)
{
    int row = blockIdx.x;
    const float2 v = ((const float2*)(x + (long long)row*D_))[threadIdx.x];
    float s  = v.x + v.y;
    float ss = v.x*v.x + v.y*v.y;
    #pragma unroll
    for (int o = 16; o; o >>= 1) {
        s  += __shfl_xor_sync(0xffffffffu, s,  o);
        ss += __shfl_xor_sync(0xffffffffu, ss, o);
    }
    __shared__ float sm_s[8], sm_ss[8];
    int w = threadIdx.x >> 5, l = threadIdx.x & 31;
    if (l == 0) { sm_s[w] = s; sm_ss[w] = ss; }
    __syncthreads();
    float ts = 0.f, tss = 0.f;
    #pragma unroll
    for (int i = 0; i < 8; i++) { ts += sm_s[i]; tss += sm_ss[i]; }
    float mu  = ts * (1.0f/D_);
    float var = tss * (1.0f/D_) - mu*mu;
    float inv = rsqrtf(var + 1e-5f);
    float2 gg = ((const float2*)g)[threadIdx.x];
    float2 bb = ((const float2*)b)[threadIdx.x];
    float ox = (v.x - mu)*inv*gg.x + bb.x;
    float oy = (v.y - mu)*inv*gg.y + bb.y;
    *(uint32_t*)(ohi + (long long)row*D_ + threadIdx.x*2) = pack2(ox, oy);
}

// ---------------- weight transpose: W[K,N] -> T[N,K] fp16 hi ---------------
__global__ __launch_bounds__(256) void wconvT_kernel(
    const float* __restrict__ W, __half* __restrict__ Thi, int K, int N)
{
    __shared__ float t[32][33];
    int tx = threadIdx.x & 31, ty = threadIdx.x >> 5;
    int k0 = blockIdx.y*32, n0 = blockIdx.x*32;
    #pragma unroll
    for (int i = 0; i < 4; i++)
        t[ty + i*8][tx] = W[(long long)(k0 + ty + i*8)*N + n0 + tx];
    __syncthreads();
    #pragma unroll
    for (int i = 0; i < 4; i++) {
        int n = n0 + ty + i*8, k = k0 + tx;
        Thi[(long long)n*K + k] = __float2half_rn(t[tx][ty + i*8]);
    }
}

// merged q/k/v weight transpose (grid.z selects which)
__global__ __launch_bounds__(256) void wconvT3_kernel(
    const float* __restrict__ Wq, const float* __restrict__ Wk,
    const float* __restrict__ Wv, __half* __restrict__ Tbase)
{
    const float* W = (blockIdx.z == 0) ? Wq : (blockIdx.z == 1) ? Wk : Wv;
    __half* Thi = Tbase + (long long)blockIdx.z * D_ * D_;
    __shared__ float t[32][33];
    int tx = threadIdx.x & 31, ty = threadIdx.x >> 5;
    int k0 = blockIdx.y*32, n0 = blockIdx.x*32;
    #pragma unroll
    for (int i = 0; i < 4; i++)
        t[ty + i*8][tx] = W[(long long)(k0 + ty + i*8)*D_ + n0 + tx];
    __syncthreads();
    #pragma unroll
    for (int i = 0; i < 4; i++) {
        int n = n0 + ty + i*8, k = k0 + tx;
        Thi[(long long)n*D_ + k] = __float2half_rn(t[tx][ty + i*8]);
    }
}

// ========= HMMA fp16 1-product GEMM: 128x128 blocks, 3-stage pipeline =======
// C = Ah[M,K] @ Bh[N,K]^T ; fp32 accum.
#define EPI_QKV   1
#define EPI_RESID 2
#define EPI_GELU  3
#define GEMM_SMEM 98304   // 3 stages x (2 tiles x 16KB)

template<int EPI>
__global__ __launch_bounds__(256) void mma_gemm(
    const __half* __restrict__ Ah, const __half* __restrict__ Bh,
    const float* __restrict__ bias0, const float* __restrict__ bias1,
    const float* __restrict__ bias2, const float* __restrict__ resid,
    float* __restrict__ Cf, __half* __restrict__ Oh,
    __half* __restrict__ qh_, __half* __restrict__ ql_,
    __half* __restrict__ kh_, __half* __restrict__ vh_,
    int M, int N, int K)
{
    extern __shared__ char smc[];
    const uint32_t sb = smem_u32(smc);
    const int t = threadIdx.x, lane = t & 31;
    const int wid = t >> 5, wm = wid & 3, wn = wid >> 2;
    const int m0 = blockIdx.y*128, n0 = blockIdx.x*128;

    float acc[2][8][4];
    #pragma unroll
    for (int f = 0; f < 2; f++)
        #pragma unroll
        for (int nf = 0; nf < 8; nf++)
            #pragma unroll
            for (int j = 0; j < 4; j++) acc[f][nf][j] = 0.f;

    auto ld_stage = [&](int st, int k0) {
        #pragma unroll
        for (int i = 0; i < 8; i++) {
            int gid = t + i*256;
            int tile = gid >> 10, idx = gid & 1023;
            int row = idx >> 3, c = idx & 7;
            const __half* sp = (tile == 0) ? Ah : Bh;
            long long rb = (tile == 0) ? m0 : n0;
            const __half* src = sp + (rb + row)*(long long)K + k0 + c*8;
            uint32_t dst = sb + st*32768 + tile*16384 + row*128 + ((c ^ (row & 7)) << 4);
            CP_ASYNC16(dst, src);
        }
    };

    const int NS = K >> 6;
    ld_stage(0, 0);  CP_COMMIT();
    ld_stage(1, 64); CP_COMMIT();
    for (int s = 0; s < NS; s++) {
        if (s + 2 < NS)      { ld_stage((s + 2)%3, (s + 2) << 6); CP_COMMIT(); CP_WAIT(2); }
        else if (s + 1 < NS) { CP_WAIT(1); }
        else                 { CP_WAIT(0); }
        __syncthreads();
        uint32_t base = sb + (s % 3)*32768;
        #pragma unroll
        for (int ks = 0; ks < 4; ks++) {
            uint32_t ah[2][4];
            #pragma unroll
            for (int f = 0; f < 2; f++) {
                int row = wm*32 + f*16 + (lane & 15);
                int ch  = ks*2 + (lane >> 4);
                uint32_t off = row*128 + ((ch ^ (row & 7)) << 4);
                ldsm_x4(ah[f], base + off);
            }
            uint32_t bh[4][4];
            #pragma unroll
            for (int g = 0; g < 4; g++) {
                int row = wn*64 + g*16 + (lane & 7) + ((lane & 16) >> 1);
                int ch  = ks*2 + ((lane >> 3) & 1);
                uint32_t off = row*128 + ((ch ^ (row & 7)) << 4);
                ldsm_x4(bh[g], base + 16384 + off);
            }
            #pragma unroll
            for (int f = 0; f < 2; f++)
                #pragma unroll
                for (int g = 0; g < 4; g++) {
                    mma16816(acc[f][2*g],   ah[f], &bh[g][0]);
                    mma16816(acc[f][2*g+1], ah[f], &bh[g][2]);
                }
        }
        __syncthreads();
    }

    // epilogue
    const int lr = lane >> 2, lc = (lane & 3)*2;
    #pragma unroll
    for (int f = 0; f < 2; f++) {
        int r0 = m0 + wm*32 + f*16 + lr;
        #pragma unroll
        for (int nf = 0; nf < 8; nf++) {
            int col = n0 + wn*64 + nf*8 + lc;
            float c0 = acc[f][nf][0], c1 = acc[f][nf][1];
            float c2 = acc[f][nf][2], c3 = acc[f][nf][3];
            if (EPI == EPI_QKV) {
                int which = col >> 9, cq = col & 511;
                const float* bp = (which == 0) ? bias0 : (which == 1) ? bias1 : bias2;
                float2 bv = *(const float2*)(bp + cq);
                c0 += bv.x; c1 += bv.y; c2 += bv.x; c3 += bv.y;
                if (which == 0) { c0 *= QSC; c1 *= QSC; c2 *= QSC; c3 *= QSC; }
                __half* dh = (which == 0) ? qh_ : (which == 1) ? kh_ : vh_;
                int hh = cq >> 6, hd = cq & 63;
                #pragma unroll
                for (int rr = 0; rr < 2; rr++) {
                    int r = r0 + rr*8;
                    int bb = r >> 11, srow = r & (S_-1);
                    long long o = (((long long)(bb*H_ + hh))*S_ + srow)*HD_ + hd;
                    uint32_t hi, lo;
                    if (rr == 0) split_pair(c0, c1, hi, lo);
                    else         split_pair(c2, c3, hi, lo);
                    *(uint32_t*)(dh + o) = hi;
                    if (which == 0) *(uint32_t*)(ql_ + o) = lo;  // only q keeps lo
                }
            } else {
                float2 bv = *(const float2*)(bias0 + col);
                c0 += bv.x; c1 += bv.y; c2 += bv.x; c3 += bv.y;
                if (EPI == EPI_RESID) {
                    float2 r0v = *(const float2*)(resid + (long long)r0*N + col);
                    float2 r1v = *(const float2*)(resid + (long long)(r0+8)*N + col);
                    *(float2*)(Cf + (long long)r0*N + col)     = make_float2(c0 + r0v.x, c1 + r0v.y);
                    *(float2*)(Cf + (long long)(r0+8)*N + col) = make_float2(c2 + r1v.x, c3 + r1v.y);
                } else { // GELU -> fp16 hi
                    c0 = 0.5f*c0*(1.0f + erff(c0*0.70710678118654752f));
                    c1 = 0.5f*c1*(1.0f + erff(c1*0.70710678118654752f));
                    c2 = 0.5f*c2*(1.0f + erff(c2*0.70710678118654752f));
                    c3 = 0.5f*c3*(1.0f + erff(c3*0.70710678118654752f));
                    *(uint32_t*)(Oh + (long long)r0*N + col)     = pack2(c0, c1);
                    *(uint32_t*)(Oh + (long long)(r0+8)*N + col) = pack2(c2, c3);
                }
            }
        }
    }
}

// == HMMA flash attention: 128-row Q tiles, QK 2-prod, PV 1-prod, exp2 dom ===
#define ATT_SMEM 81920   // Q hi/lo 32KB + 3 stages x (K 8KB + V 8KB)

__global__ __launch_bounds__(256) void attn_mma_kernel(
    const __half* __restrict__ Qh, const __half* __restrict__ Ql,
    const __half* __restrict__ Kh, const __half* __restrict__ Vh,
    const __half* __restrict__ bias, __half* __restrict__ Ohi)
{
    extern __shared__ char smc[];
    const uint32_t sb = smem_u32(smc);
    const int t = threadIdx.x, lane = t & 31, w = t >> 5;   // 8 warps
    const int q0 = blockIdx.x*128, hh = blockIdx.y, bb = blockIdx.z;
    const long long bhs = (long long)(bb*H_ + hh)*S_;
    const int lr = lane >> 2, lc = (lane & 3)*2;

    auto ld_stage = [&](int st, int kt) {
        uint32_t base = sb + 32768 + st*16384;
        #pragma unroll
        for (int i = 0; i < 4; i++) {
            int gid = t + i*256;
            int tile = gid >> 9, idx = gid & 511;   // 0=Kh, 1=Vh
            int row = idx >> 3, c = idx & 7;
            const __half* sp = tile ? Vh : Kh;
            const __half* src = sp + (bhs + kt*64 + row)*HD_ + c*8;
            uint32_t dst = base + tile*8192 + row*128 + ((c ^ (row & 7)) << 4);
            CP_ASYNC16(dst, src);
        }
    };

    // G0: Q hi/lo + K/V stage 0
    #pragma unroll
    for (int i = 0; i < 8; i++) {
        int gid = t + i*256;
        int tile = gid >> 10, idx = gid & 1023;
        int row = idx >> 3, c = idx & 7;
        const __half* sp = tile ? Ql : Qh;
        const __half* src = sp + (bhs + q0 + row)*HD_ + c*8;
        uint32_t dst = sb + tile*16384 + row*128 + ((c ^ (row & 7)) << 4);
        CP_ASYNC16(dst, src);
    }
    ld_stage(0, 0);
    CP_COMMIT();
    ld_stage(1, 1);
    CP_COMMIT();
    CP_WAIT(1);
    __syncthreads();

    // Q frags (persistent): each warp owns 16 q-rows
    uint32_t qfh[4][4], qfl[4][4];
    #pragma unroll
    for (int ks = 0; ks < 4; ks++) {
        int row = w*16 + (lane & 15);
        int ch  = ks*2 + (lane >> 4);
        uint32_t off = row*128 + ((ch ^ (row & 7)) << 4);
        ldsm_x4(qfh[ks], sb + off);
        ldsm_x4(qfl[ks], sb + 16384 + off);
    }

    float Oacc[8][4];
    #pragma unroll
    for (int nf = 0; nf < 8; nf++)
        #pragma unroll
        for (int j = 0; j < 4; j++) Oacc[nf][j] = 0.f;
    float ms0 = -3e38f, ms1 = -3e38f, ls0 = 0.f, ls1 = 0.f;

    const int NT = S_/64;
    for (int kt = 0; kt < NT; kt++) {
        if (kt + 2 < NT)      { ld_stage((kt + 2)%3, kt + 2); CP_COMMIT(); CP_WAIT(2); }
        else if (kt + 1 < NT) { CP_WAIT(1); }
        else                  { CP_WAIT(0); }
        __syncthreads();
        uint32_t base = sb + 32768 + (kt % 3)*16384;

        // S = Q @ K^T (Qh*Kh + Ql*Kh), pre-scaled into log2 domain
        float sacc[8][4];
        #pragma unroll
        for (int nf = 0; nf < 8; nf++)
            #pragma unroll
            for (int j = 0; j < 4; j++) sacc[nf][j] = 0.f;
        #pragma unroll
        for (int ks = 0; ks < 4; ks++) {
            uint32_t kh4[4][4];
            #pragma unroll
            for (int g = 0; g < 4; g++) {
                int row = g*16 + (lane & 7) + ((lane & 16) >> 1);
                int ch  = ks*2 + ((lane >> 3) & 1);
                uint32_t off = row*128 + ((ch ^ (row & 7)) << 4);
                ldsm_x4(kh4[g], base + off);
            }
            #pragma unroll
            for (int g = 0; g < 4; g++) {
                mma16816(sacc[2*g],   qfh[ks], &kh4[g][0]);
                mma16816(sacc[2*g+1], qfh[ks], &kh4[g][2]);
                mma16816(sacc[2*g],   qfl[ks], &kh4[g][0]);
                mma16816(sacc[2*g+1], qfl[ks], &kh4[g][2]);
            }
        }

        // bias add (log2-domain), row maxes
        int r0 = q0 + w*16 + lr;
        const __half* bp0 = bias + ((long long)bb*S_ + r0)*S_ + kt*64 + lc;
        const __half* bp1 = bp0 + 8*S_;
        float rm0 = -3e38f, rm1 = -3e38f;
        #pragma unroll
        for (int nf = 0; nf < 8; nf++) {
            float2 b0 = __half22float2(*(const __half2*)(bp0 + nf*8));
            float2 b1 = __half22float2(*(const __half2*)(bp1 + nf*8));
            sacc[nf][0] += b0.x;
            sacc[nf][1] += b0.y;
            sacc[nf][2] += b1.x;
            sacc[nf][3] += b1.y;
            rm0 = fmaxf(rm0, fmaxf(sacc[nf][0], sacc[nf][1]));
            rm1 = fmaxf(rm1, fmaxf(sacc[nf][2], sacc[nf][3]));
        }
        rm0 = fmaxf(rm0, __shfl_xor_sync(0xffffffffu, rm0, 1));
        rm0 = fmaxf(rm0, __shfl_xor_sync(0xffffffffu, rm0, 2));
        rm1 = fmaxf(rm1, __shfl_xor_sync(0xffffffffu, rm1, 1));
        rm1 = fmaxf(rm1, __shfl_xor_sync(0xffffffffu, rm1, 2));
        float mn0 = fmaxf(ms0, rm0), mn1 = fmaxf(ms1, rm1);
        float al0 = ex2f(ms0 - mn0), al1 = ex2f(ms1 - mn1);
        ms0 = mn0; ms1 = mn1;
        float rs0 = 0.f, rs1 = 0.f;
        #pragma unroll
        for (int nf = 0; nf < 8; nf++) {
            sacc[nf][0] = ex2f(sacc[nf][0] - mn0);
            sacc[nf][1] = ex2f(sacc[nf][1] - mn0);
            sacc[nf][2] = ex2f(sacc[nf][2] - mn1);
            sacc[nf][3] = ex2f(sacc[nf][3] - mn1);
            rs0 += sacc[nf][0] + sacc[nf][1];
            rs1 += sacc[nf][2] + sacc[nf][3];
        }
        rs0 += __shfl_xor_sync(0xffffffffu, rs0, 1);
        rs0 += __shfl_xor_sync(0xffffffffu, rs0, 2);
        rs1 += __shfl_xor_sync(0xffffffffu, rs1, 1);
        rs1 += __shfl_xor_sync(0xffffffffu, rs1, 2);
        ls0 = ls0*al0 + rs0;
        ls1 = ls1*al1 + rs1;
        #pragma unroll
        for (int nf = 0; nf < 8; nf++) {
            Oacc[nf][0] *= al0; Oacc[nf][1] *= al0;
            Oacc[nf][2] *= al1; Oacc[nf][3] *= al1;
        }

        // P -> fp16 hi frags (C-frag layout == A-frag layout)
        uint32_t ph[4][4];
        #pragma unroll
        for (int j = 0; j < 4; j++) {
            ph[j][0] = pack2(sacc[2*j][0],   sacc[2*j][1]);
            ph[j][1] = pack2(sacc[2*j][2],   sacc[2*j][3]);
            ph[j][2] = pack2(sacc[2*j+1][0], sacc[2*j+1][1]);
            ph[j][3] = pack2(sacc[2*j+1][2], sacc[2*j+1][3]);
        }

        // O += Ph @ Vh (1-product), V via trans ldmatrix
        #pragma unroll
        for (int j = 0; j < 4; j++) {
            uint32_t vh4[4][4];
            #pragma unroll
            for (int g = 0; g < 4; g++) {
                int row = j*16 + (lane & 7) + (lane & 8);
                int ch  = g*2 + ((lane >> 4) & 1);
                uint32_t off = row*128 + ((ch ^ (row & 7)) << 4);
                ldsm_x4_t(vh4[g], base + 8192 + off);
            }
            #pragma unroll
            for (int g = 0; g < 4; g++) {
                mma16816(Oacc[2*g],   ph[j], &vh4[g][0]);
                mma16816(Oacc[2*g+1], ph[j], &vh4[g][2]);
            }
        }
        __syncthreads();
    }

    // epilogue -> fp16 hi into [B,S,D]
    float inv0 = 1.0f/ls0, inv1 = 1.0f/ls1;
    long long rowA = ((long long)bb*S_ + q0 + w*16 + lr)*D_ + hh*HD_;
    long long rowB = rowA + 8LL*D_;
    #pragma unroll
    for (int nf = 0; nf < 8; nf++) {
        int hd = nf*8 + lc;
        *(uint32_t*)(Ohi + rowA + hd) = pack2(Oacc[nf][0]*inv0, Oacc[nf][1]*inv0);
        *(uint32_t*)(Ohi + rowB + hd) = pack2(Oacc[nf][2]*inv1, Oacc[nf][3]*inv1);
    }
}

// ---------------------------- launch ---------------------------------------
extern "C" void kernel_launch(void* const* d_in, const int* in_sizes, int n_in,
                              void* d_out, int out_size)
{
    const float* x    = (const float*)d_in[0];
    const int*   adj  = (const int*)  d_in[1];
    const float* edge = (const float*)d_in[2];
    const float* ln1g = (const float*)d_in[3];
    const float* ln1b = (const float*)d_in[4];
    const float* ln2g = (const float*)d_in[5];
    const float* ln2b = (const float*)d_in[6];
    const float* wq = (const float*)d_in[7];  const float* bq = (const float*)d_in[8];
    const float* wk = (const float*)d_in[9];  const float* bk = (const float*)d_in[10];
    const float* wv = (const float*)d_in[11]; const float* bv = (const float*)d_in[12];
    const float* wo = (const float*)d_in[13]; const float* bo = (const float*)d_in[14];
    const float* w1 = (const float*)d_in[15]; const float* b1 = (const float*)d_in[16];
    const float* w2 = (const float*)d_in[17]; const float* b2 = (const float*)d_in[18];
    float* out = (float*)d_out;

    float *x1;
    __half *biasc;
    cudaGetSymbolAddress((void**)&x1,    g_x1);
    cudaGetSymbolAddress((void**)&biasc, g_bias);
    __half *pah, *qah, *qh, *ql, *kh, *vh;
    __half *wqkvh, *woh, *w1h, *w2h;
    cudaGetSymbolAddress((void**)&pah, g_pa_hi);
    cudaGetSymbolAddress((void**)&qah, g_qa_hi);
    cudaGetSymbolAddress((void**)&qh, g_qh); cudaGetSymbolAddress((void**)&ql, g_ql);
    cudaGetSymbolAddress((void**)&kh, g_kh); cudaGetSymbolAddress((void**)&vh, g_vh);
    cudaGetSymbolAddress((void**)&wqkvh, g_wqkv_hi);
    cudaGetSymbolAddress((void**)&woh, g_wo_hi);
    cudaGetSymbolAddress((void**)&w1h, g_w1_hi);
    cudaGetSymbolAddress((void**)&w2h, g_w2_hi);

    cudaFuncSetAttribute((const void*)mma_gemm<EPI_QKV>,
        cudaFuncAttributeMaxDynamicSharedMemorySize, GEMM_SMEM);
    cudaFuncSetAttribute((const void*)mma_gemm<EPI_RESID>,
        cudaFuncAttributeMaxDynamicSharedMemorySize, GEMM_SMEM);
    cudaFuncSetAttribute((const void*)mma_gemm<EPI_GELU>,
        cudaFuncAttributeMaxDynamicSharedMemorySize, GEMM_SMEM);
    cudaFuncSetAttribute(attn_mma_kernel,
        cudaFuncAttributeMaxDynamicSharedMemorySize, ATT_SMEM);

    // side stream + events, created once (outside graph capture on first call)
    static cudaStream_t s1 = nullptr;
    static cudaEvent_t evFork = nullptr, evJoinB = nullptr, evJoinW = nullptr;
    if (!s1) {
        cudaStreamCreateWithFlags(&s1, cudaStreamNonBlocking);
        cudaEventCreateWithFlags(&evFork, cudaEventDisableTiming);
        cudaEventCreateWithFlags(&evJoinB, cudaEventDisableTiming);
        cudaEventCreateWithFlags(&evJoinW, cudaEventDisableTiming);
    }

    // fork: side stream does bias (needed before attn), then wo/w1/w2 convs
    cudaEventRecord(evFork, 0);
    cudaStreamWaitEvent(s1, evFork, 0);
    dim3 wb(256);
    bias_kernel<<<(B_*S_*S_/4)/256, 256, 0, s1>>>(
        (const int4*)adj, (const float4*)edge, (uint2*)biasc);
    cudaEventRecord(evJoinB, s1);
    wconvT_kernel<<<dim3(16,16), wb, 0, s1>>>(wo, woh, D_, D_);
    wconvT_kernel<<<dim3(64,16), wb, 0, s1>>>(w1, w1h, D_, DFF);
    wconvT_kernel<<<dim3(16,64), wb, 0, s1>>>(w2, w2h, DFF, D_);
    cudaEventRecord(evJoinW, s1);

    // main: LN1 + merged qkv weight conversion + QKV gemm (1-product)
    ln_f16_kernel<<<MTOK, 256>>>(x, ln1g, ln1b, pah);
    wconvT3_kernel<<<dim3(16,16,3), wb>>>(wq, wk, wv, wqkvh);
    mma_gemm<EPI_QKV><<<dim3(12, 32), 256, GEMM_SMEM>>>(
        pah, wqkvh, bq, bk, bv, nullptr, nullptr, nullptr,
        qh, ql, kh, vh, MTOK, 3*D_, D_);

    // join bias, then attention (128-row Q tiles)
    cudaStreamWaitEvent(0, evJoinB, 0);
    attn_mma_kernel<<<dim3(S_/128, H_, B_), 256, ATT_SMEM>>>(
        qh, ql, kh, vh, biasc, pah);

    // join weights, then O projection + residual -> x1 (fp32)
    cudaStreamWaitEvent(0, evJoinW, 0);
    mma_gemm<EPI_RESID><<<dim3(4, 32), 256, GEMM_SMEM>>>(
        pah, woh, bo, nullptr, nullptr, x, x1, nullptr,
        nullptr, nullptr, nullptr, nullptr, MTOK, D_, D_);

    // LN2 -> fp16 hi
    ln_f16_kernel<<<MTOK, 256>>>(x1, ln2g, ln2b, pah);

    // MLP up + exact GELU -> fp16 hi
    mma_gemm<EPI_GELU><<<dim3(16, 32), 256, GEMM_SMEM>>>(
        pah, w1h, b1, nullptr, nullptr, nullptr, nullptr, qah,
        nullptr, nullptr, nullptr, nullptr, MTOK, DFF, D_);

    // MLP down + residual -> out
    mma_gemm<EPI_RESID><<<dim3(4, 32), 256, GEMM_SMEM>>>(
        qah, w2h, b2, nullptr, nullptr, x1, out, nullptr,
        nullptr, nullptr, nullptr, nullptr, MTOK, D_, DFF);
}

// round 8
// speedup vs baseline: 7.1221x; 1.0804x over previous
#include <cuda_runtime.h>
#include <cuda_fp16.h>
#include <math.h>
#include <cstdint>

#define B_   2
#define S_   2048
#define D_   512
#define H_   8
#define HD_  64
#define MTOK (B_*S_)      // 4096
#define DFF  (4*D_)       // 2048

#define QSC  0.1803368801111f   // 0.125 * log2(e)
#define BSC  0.1442695040889f   // 0.1  * log2(e)
#define MASKV (-43281.0f)       // -30000 * log2(e), fits fp16

// ---------------- scratch (device globals; no allocation allowed) ----------
__device__ float  g_x1  [MTOK*D_];
__device__ __half g_bias[(long long)B_*S_*S_];   // mask+edge bias, pre-scaled by log2e

// fp16 activation buffers
__device__ __half g_pa_hi[MTOK*D_];              // nx / att / n2
__device__ __half g_qa_hi[MTOK*DFF];             // mlp hidden

// q (pre-scaled by QSC), k, v — all hi-only, [B,H,S,HD]
__device__ __half g_qh[MTOK*D_];
__device__ __half g_kh[MTOK*D_];
__device__ __half g_vh[MTOK*D_];

// fp16 transposed weights [N][K]
__device__ __half g_wqkv_hi[3*D_*D_];
__device__ __half g_wo_hi[D_*D_];
__device__ __half g_w1_hi[DFF*D_];
__device__ __half g_w2_hi[D_*DFF];

// ======================= PTX helpers ========================================
__device__ __forceinline__ uint32_t smem_u32(const void* p) {
    uint32_t a;
    asm("{ .reg .u64 t; cvta.to.shared.u64 t, %1; cvt.u32.u64 %0, t; }"
        : "=r"(a) : "l"(p));
    return a;
}
#define CP_ASYNC16(dst, src) \
    asm volatile("cp.async.cg.shared.global [%0], [%1], 16;" :: "r"(dst), "l"(src))
#define CP_COMMIT() asm volatile("cp.async.commit_group;" ::: "memory")
#define CP_WAIT(n)  asm volatile("cp.async.wait_group %0;" :: "n"(n) : "memory")

__device__ __forceinline__ void ldsm_x4(uint32_t* r, uint32_t a) {
    asm volatile("ldmatrix.sync.aligned.m8n8.x4.shared.b16 {%0,%1,%2,%3}, [%4];"
        : "=r"(r[0]), "=r"(r[1]), "=r"(r[2]), "=r"(r[3]) : "r"(a));
}
__device__ __forceinline__ void ldsm_x4_t(uint32_t* r, uint32_t a) {
    asm volatile("ldmatrix.sync.aligned.m8n8.x4.trans.shared.b16 {%0,%1,%2,%3}, [%4];"
        : "=r"(r[0]), "=r"(r[1]), "=r"(r[2]), "=r"(r[3]) : "r"(a));
}
__device__ __forceinline__ void mma16816(float* c, const uint32_t* a, const uint32_t* b) {
    asm volatile("mma.sync.aligned.m16n8k16.row.col.f32.f16.f16.f32 "
        "{%0,%1,%2,%3}, {%4,%5,%6,%7}, {%8,%9}, {%0,%1,%2,%3};"
        : "+f"(c[0]), "+f"(c[1]), "+f"(c[2]), "+f"(c[3])
        : "r"(a[0]), "r"(a[1]), "r"(a[2]), "r"(a[3]), "r"(b[0]), "r"(b[1]));
}
__device__ __forceinline__ float ex2f(float x) {
    float y; asm("ex2.approx.f32 %0, %1;" : "=f"(y) : "f"(x)); return y;
}
__device__ __forceinline__ uint32_t packh(__half a, __half b) {
    return ((uint32_t)*(uint16_t*)&a) | ((uint32_t)*(uint16_t*)&b << 16);
}
__device__ __forceinline__ uint32_t pack2(float a, float b) {
    return packh(__float2half_rn(a), __float2half_rn(b));
}

// ---------------- bias precompute: adj/edge -> fp16, pre-scaled by log2e ----
__global__ __launch_bounds__(256) void bias_kernel(
    const int4* __restrict__ adj, const float4* __restrict__ edge,
    uint2* __restrict__ out)
{
    int i = blockIdx.x*256 + threadIdx.x;
    int4 a = adj[i]; float4 e = edge[i];
    uint2 o;
    o.x = pack2(a.x ? BSC*e.x : MASKV, a.y ? BSC*e.y : MASKV);
    o.y = pack2(a.z ? BSC*e.z : MASKV, a.w ? BSC*e.w : MASKV);
    out[i] = o;
}

// ---------------- LayerNorm -> fp16 hi ---------------------------------------
__global__ __launch_bounds__(256) void ln_f16_kernel(
    const float* __restrict__ x, const float* __restrict__ g,
    const float* __restrict__ b, __half* __restrict__ ohi)
{
    int row = blockIdx.x;
    const float2 v = ((const float2*)(x + (long long)row*D_))[threadIdx.x];
    float s  = v.x + v.y;
    float ss = v.x*v.x + v.y*v.y;
    #pragma unroll
    for (int o = 16; o; o >>= 1) {
        s  += __shfl_xor_sync(0xffffffffu, s,  o);
        ss += __shfl_xor_sync(0xffffffffu, ss, o);
    }
    __shared__ float sm_s[8], sm_ss[8];
    int w = threadIdx.x >> 5, l = threadIdx.x & 31;
    if (l == 0) { sm_s[w] = s; sm_ss[w] = ss; }
    __syncthreads();
    float ts = 0.f, tss = 0.f;
    #pragma unroll
    for (int i = 0; i < 8; i++) { ts += sm_s[i]; tss += sm_ss[i]; }
    float mu  = ts * (1.0f/D_);
    float var = tss * (1.0f/D_) - mu*mu;
    float inv = rsqrtf(var + 1e-5f);
    float2 gg = ((const float2*)g)[threadIdx.x];
    float2 bb = ((const float2*)b)[threadIdx.x];
    float ox = (v.x - mu)*inv*gg.x + bb.x;
    float oy = (v.y - mu)*inv*gg.y + bb.y;
    *(uint32_t*)(ohi + (long long)row*D_ + threadIdx.x*2) = pack2(ox, oy);
}

// ---------------- weight transpose: W[K,N] -> T[N,K] fp16 hi ---------------
__global__ __launch_bounds__(256) void wconvT_kernel(
    const float* __restrict__ W, __half* __restrict__ Thi, int K, int N)
{
    __shared__ float t[32][33];
    int tx = threadIdx.x & 31, ty = threadIdx.x >> 5;
    int k0 = blockIdx.y*32, n0 = blockIdx.x*32;
    #pragma unroll
    for (int i = 0; i < 4; i++)
        t[ty + i*8][tx] = W[(long long)(k0 + ty + i*8)*N + n0 + tx];
    __syncthreads();
    #pragma unroll
    for (int i = 0; i < 4; i++) {
        int n = n0 + ty + i*8, k = k0 + tx;
        Thi[(long long)n*K + k] = __float2half_rn(t[tx][ty + i*8]);
    }
}

// merged q/k/v weight transpose (grid.z selects which)
__global__ __launch_bounds__(256) void wconvT3_kernel(
    const float* __restrict__ Wq, const float* __restrict__ Wk,
    const float* __restrict__ Wv, __half* __restrict__ Tbase)
{
    const float* W = (blockIdx.z == 0) ? Wq : (blockIdx.z == 1) ? Wk : Wv;
    __half* Thi = Tbase + (long long)blockIdx.z * D_ * D_;
    __shared__ float t[32][33];
    int tx = threadIdx.x & 31, ty = threadIdx.x >> 5;
    int k0 = blockIdx.y*32, n0 = blockIdx.x*32;
    #pragma unroll
    for (int i = 0; i < 4; i++)
        t[ty + i*8][tx] = W[(long long)(k0 + ty + i*8)*D_ + n0 + tx];
    __syncthreads();
    #pragma unroll
    for (int i = 0; i < 4; i++) {
        int n = n0 + ty + i*8, k = k0 + tx;
        Thi[(long long)n*D_ + k] = __float2half_rn(t[tx][ty + i*8]);
    }
}

// ========= HMMA fp16 1-product GEMM: 128x128 blocks, 3-stage pipeline =======
#define EPI_QKV   1
#define EPI_RESID 2
#define EPI_GELU  3
#define GEMM_SMEM 98304   // 3 stages x (2 tiles x 16KB)

template<int EPI>
__global__ __launch_bounds__(256) void mma_gemm(
    const __half* __restrict__ Ah, const __half* __restrict__ Bh,
    const float* __restrict__ bias0, const float* __restrict__ bias1,
    const float* __restrict__ bias2, const float* __restrict__ resid,
    float* __restrict__ Cf, __half* __restrict__ Oh,
    __half* __restrict__ qh_, __half* __restrict__ kh_, __half* __restrict__ vh_,
    int M, int N, int K)
{
    extern __shared__ char smc[];
    const uint32_t sb = smem_u32(smc);
    const int t = threadIdx.x, lane = t & 31;
    const int wid = t >> 5, wm = wid & 3, wn = wid >> 2;
    const int m0 = blockIdx.y*128, n0 = blockIdx.x*128;

    float acc[2][8][4];
    #pragma unroll
    for (int f = 0; f < 2; f++)
        #pragma unroll
        for (int nf = 0; nf < 8; nf++)
            #pragma unroll
            for (int j = 0; j < 4; j++) acc[f][nf][j] = 0.f;

    auto ld_stage = [&](int st, int k0) {
        #pragma unroll
        for (int i = 0; i < 8; i++) {
            int gid = t + i*256;
            int tile = gid >> 10, idx = gid & 1023;
            int row = idx >> 3, c = idx & 7;
            const __half* sp = (tile == 0) ? Ah : Bh;
            long long rb = (tile == 0) ? m0 : n0;
            const __half* src = sp + (rb + row)*(long long)K + k0 + c*8;
            uint32_t dst = sb + st*32768 + tile*16384 + row*128 + ((c ^ (row & 7)) << 4);
            CP_ASYNC16(dst, src);
        }
    };

    const int NS = K >> 6;
    ld_stage(0, 0);  CP_COMMIT();
    ld_stage(1, 64); CP_COMMIT();
    for (int s = 0; s < NS; s++) {
        if (s + 2 < NS)      { ld_stage((s + 2)%3, (s + 2) << 6); CP_COMMIT(); CP_WAIT(2); }
        else if (s + 1 < NS) { CP_WAIT(1); }
        else                 { CP_WAIT(0); }
        __syncthreads();
        uint32_t base = sb + (s % 3)*32768;
        #pragma unroll
        for (int ks = 0; ks < 4; ks++) {
            uint32_t ah[2][4];
            #pragma unroll
            for (int f = 0; f < 2; f++) {
                int row = wm*32 + f*16 + (lane & 15);
                int ch  = ks*2 + (lane >> 4);
                uint32_t off = row*128 + ((ch ^ (row & 7)) << 4);
                ldsm_x4(ah[f], base + off);
            }
            uint32_t bh[4][4];
            #pragma unroll
            for (int g = 0; g < 4; g++) {
                int row = wn*64 + g*16 + (lane & 7) + ((lane & 16) >> 1);
                int ch  = ks*2 + ((lane >> 3) & 1);
                uint32_t off = row*128 + ((ch ^ (row & 7)) << 4);
                ldsm_x4(bh[g], base + 16384 + off);
            }
            #pragma unroll
            for (int f = 0; f < 2; f++)
                #pragma unroll
                for (int g = 0; g < 4; g++) {
                    mma16816(acc[f][2*g],   ah[f], &bh[g][0]);
                    mma16816(acc[f][2*g+1], ah[f], &bh[g][2]);
                }
        }
        __syncthreads();
    }

    // epilogue
    const int lr = lane >> 2, lc = (lane & 3)*2;
    #pragma unroll
    for (int f = 0; f < 2; f++) {
        int r0 = m0 + wm*32 + f*16 + lr;
        #pragma unroll
        for (int nf = 0; nf < 8; nf++) {
            int col = n0 + wn*64 + nf*8 + lc;
            float c0 = acc[f][nf][0], c1 = acc[f][nf][1];
            float c2 = acc[f][nf][2], c3 = acc[f][nf][3];
            if (EPI == EPI_QKV) {
                int which = col >> 9, cq = col & 511;
                const float* bp = (which == 0) ? bias0 : (which == 1) ? bias1 : bias2;
                float2 bv = *(const float2*)(bp + cq);
                c0 += bv.x; c1 += bv.y; c2 += bv.x; c3 += bv.y;
                if (which == 0) { c0 *= QSC; c1 *= QSC; c2 *= QSC; c3 *= QSC; }
                __half* dh = (which == 0) ? qh_ : (which == 1) ? kh_ : vh_;
                int hh = cq >> 6, hd = cq & 63;
                #pragma unroll
                for (int rr = 0; rr < 2; rr++) {
                    int r = r0 + rr*8;
                    int bb = r >> 11, srow = r & (S_-1);
                    long long o = (((long long)(bb*H_ + hh))*S_ + srow)*HD_ + hd;
                    *(uint32_t*)(dh + o) = (rr == 0) ? pack2(c0, c1) : pack2(c2, c3);
                }
            } else {
                float2 bv = *(const float2*)(bias0 + col);
                c0 += bv.x; c1 += bv.y; c2 += bv.x; c3 += bv.y;
                if (EPI == EPI_RESID) {
                    float2 r0v = *(const float2*)(resid + (long long)r0*N + col);
                    float2 r1v = *(const float2*)(resid + (long long)(r0+8)*N + col);
                    *(float2*)(Cf + (long long)r0*N + col)     = make_float2(c0 + r0v.x, c1 + r0v.y);
                    *(float2*)(Cf + (long long)(r0+8)*N + col) = make_float2(c2 + r1v.x, c3 + r1v.y);
                } else { // GELU -> fp16 hi
                    c0 = 0.5f*c0*(1.0f + erff(c0*0.70710678118654752f));
                    c1 = 0.5f*c1*(1.0f + erff(c1*0.70710678118654752f));
                    c2 = 0.5f*c2*(1.0f + erff(c2*0.70710678118654752f));
                    c3 = 0.5f*c3*(1.0f + erff(c3*0.70710678118654752f));
                    *(uint32_t*)(Oh + (long long)r0*N + col)     = pack2(c0, c1);
                    *(uint32_t*)(Oh + (long long)(r0+8)*N + col) = pack2(c2, c3);
                }
            }
        }
    }
}

// == HMMA flash attention: 128-row Q tiles, QK/PV 1-product, 4-stage pipe ====
#define ATT_SMEM 81920   // Q 16KB + 4 stages x (K 8KB + V 8KB)

__global__ __launch_bounds__(256) void attn_mma_kernel(
    const __half* __restrict__ Qh, const __half* __restrict__ Kh,
    const __half* __restrict__ Vh, const __half* __restrict__ bias,
    __half* __restrict__ Ohi)
{
    extern __shared__ char smc[];
    const uint32_t sb = smem_u32(smc);
    const int t = threadIdx.x, lane = t & 31, w = t >> 5;   // 8 warps
    const int q0 = blockIdx.x*128, hh = blockIdx.y, bb = blockIdx.z;
    const long long bhs = (long long)(bb*H_ + hh)*S_;
    const int lr = lane >> 2, lc = (lane & 3)*2;

    auto ld_stage = [&](int st, int kt) {
        uint32_t base = sb + 16384 + st*16384;
        #pragma unroll
        for (int i = 0; i < 4; i++) {
            int gid = t + i*256;
            int tile = gid >> 9, idx = gid & 511;   // 0=Kh, 1=Vh
            int row = idx >> 3, c = idx & 7;
            const __half* sp = tile ? Vh : Kh;
            const __half* src = sp + (bhs + kt*64 + row)*HD_ + c*8;
            uint32_t dst = base + tile*8192 + row*128 + ((c ^ (row & 7)) << 4);
            CP_ASYNC16(dst, src);
        }
    };

    // Q (with stage 0), then stages 1,2
    #pragma unroll
    for (int i = 0; i < 4; i++) {
        int idx = t + i*256;
        int row = idx >> 3, c = idx & 7;
        const __half* src = Qh + (bhs + q0 + row)*HD_ + c*8;
        uint32_t dst = sb + row*128 + ((c ^ (row & 7)) << 4);
        CP_ASYNC16(dst, src);
    }
    ld_stage(0, 0); CP_COMMIT();
    ld_stage(1, 1); CP_COMMIT();
    ld_stage(2, 2); CP_COMMIT();
    CP_WAIT(2);
    __syncthreads();

    // Q frags (persistent): each warp owns 16 q-rows
    uint32_t qfh[4][4];
    #pragma unroll
    for (int ks = 0; ks < 4; ks++) {
        int row = w*16 + (lane & 15);
        int ch  = ks*2 + (lane >> 4);
        uint32_t off = row*128 + ((ch ^ (row & 7)) << 4);
        ldsm_x4(qfh[ks], sb + off);
    }

    float Oacc[8][4];
    #pragma unroll
    for (int nf = 0; nf < 8; nf++)
        #pragma unroll
        for (int j = 0; j < 4; j++) Oacc[nf][j] = 0.f;
    float ms0 = -3e38f, ms1 = -3e38f, ls0 = 0.f, ls1 = 0.f;

    const int NT = S_/64;
    for (int kt = 0; kt < NT; kt++) {
        if (kt + 3 < NT)      { ld_stage((kt + 3) & 3, kt + 3); CP_COMMIT(); CP_WAIT(3); }
        else if (kt + 2 < NT) { CP_WAIT(2); }
        else if (kt + 1 < NT) { CP_WAIT(1); }
        else                  { CP_WAIT(0); }
        __syncthreads();
        uint32_t base = sb + 16384 + (kt & 3)*16384;

        // S = Q @ K^T (1-product, log2 domain)
        float sacc[8][4];
        #pragma unroll
        for (int nf = 0; nf < 8; nf++)
            #pragma unroll
            for (int j = 0; j < 4; j++) sacc[nf][j] = 0.f;
        #pragma unroll
        for (int ks = 0; ks < 4; ks++) {
            uint32_t kh4[4][4];
            #pragma unroll
            for (int g = 0; g < 4; g++) {
                int row = g*16 + (lane & 7) + ((lane & 16) >> 1);
                int ch  = ks*2 + ((lane >> 3) & 1);
                uint32_t off = row*128 + ((ch ^ (row & 7)) << 4);
                ldsm_x4(kh4[g], base + off);
            }
            #pragma unroll
            for (int g = 0; g < 4; g++) {
                mma16816(sacc[2*g],   qfh[ks], &kh4[g][0]);
                mma16816(sacc[2*g+1], qfh[ks], &kh4[g][2]);
            }
        }

        // bias add (log2-domain), row maxes
        int r0 = q0 + w*16 + lr;
        const __half* bp0 = bias + ((long long)bb*S_ + r0)*S_ + kt*64 + lc;
        const __half* bp1 = bp0 + 8*S_;
        float rm0 = -3e38f, rm1 = -3e38f;
        #pragma unroll
        for (int nf = 0; nf < 8; nf++) {
            float2 b0 = __half22float2(*(const __half2*)(bp0 + nf*8));
            float2 b1 = __half22float2(*(const __half2*)(bp1 + nf*8));
            sacc[nf][0] += b0.x;
            sacc[nf][1] += b0.y;
            sacc[nf][2] += b1.x;
            sacc[nf][3] += b1.y;
            rm0 = fmaxf(rm0, fmaxf(sacc[nf][0], sacc[nf][1]));
            rm1 = fmaxf(rm1, fmaxf(sacc[nf][2], sacc[nf][3]));
        }
        rm0 = fmaxf(rm0, __shfl_xor_sync(0xffffffffu, rm0, 1));
        rm0 = fmaxf(rm0, __shfl_xor_sync(0xffffffffu, rm0, 2));
        rm1 = fmaxf(rm1, __shfl_xor_sync(0xffffffffu, rm1, 1));
        rm1 = fmaxf(rm1, __shfl_xor_sync(0xffffffffu, rm1, 2));
        float mn0 = fmaxf(ms0, rm0), mn1 = fmaxf(ms1, rm1);
        bool newmax = (mn0 > ms0) || (mn1 > ms1);
        float al0 = ex2f(ms0 - mn0), al1 = ex2f(ms1 - mn1);
        ms0 = mn0; ms1 = mn1;
        float rs0 = 0.f, rs1 = 0.f;
        #pragma unroll
        for (int nf = 0; nf < 8; nf++) {
            sacc[nf][0] = ex2f(sacc[nf][0] - mn0);
            sacc[nf][1] = ex2f(sacc[nf][1] - mn0);
            sacc[nf][2] = ex2f(sacc[nf][2] - mn1);
            sacc[nf][3] = ex2f(sacc[nf][3] - mn1);
            rs0 += sacc[nf][0] + sacc[nf][1];
            rs1 += sacc[nf][2] + sacc[nf][3];
        }
        rs0 += __shfl_xor_sync(0xffffffffu, rs0, 1);
        rs0 += __shfl_xor_sync(0xffffffffu, rs0, 2);
        rs1 += __shfl_xor_sync(0xffffffffu, rs1, 1);
        rs1 += __shfl_xor_sync(0xffffffffu, rs1, 2);
        ls0 = ls0*al0 + rs0;
        ls1 = ls1*al1 + rs1;
        if (__any_sync(0xffffffffu, newmax)) {
            #pragma unroll
            for (int nf = 0; nf < 8; nf++) {
                Oacc[nf][0] *= al0; Oacc[nf][1] *= al0;
                Oacc[nf][2] *= al1; Oacc[nf][3] *= al1;
            }
        }

        // P -> fp16 frags (C-frag layout == A-frag layout)
        uint32_t ph[4][4];
        #pragma unroll
        for (int j = 0; j < 4; j++) {
            ph[j][0] = pack2(sacc[2*j][0],   sacc[2*j][1]);
            ph[j][1] = pack2(sacc[2*j][2],   sacc[2*j][3]);
            ph[j][2] = pack2(sacc[2*j+1][0], sacc[2*j+1][1]);
            ph[j][3] = pack2(sacc[2*j+1][2], sacc[2*j+1][3]);
        }

        // O += Ph @ Vh (1-product), V via trans ldmatrix
        #pragma unroll
        for (int j = 0; j < 4; j++) {
            uint32_t vh4[4][4];
            #pragma unroll
            for (int g = 0; g < 4; g++) {
                int row = j*16 + (lane & 7) + (lane & 8);
                int ch  = g*2 + ((lane >> 4) & 1);
                uint32_t off = row*128 + ((ch ^ (row & 7)) << 4);
                ldsm_x4_t(vh4[g], base + 8192 + off);
            }
            #pragma unroll
            for (int g = 0; g < 4; g++) {
                mma16816(Oacc[2*g],   ph[j], &vh4[g][0]);
                mma16816(Oacc[2*g+1], ph[j], &vh4[g][2]);
            }
        }
        __syncthreads();
    }

    // epilogue -> fp16 hi into [B,S,D]
    float inv0 = 1.0f/ls0, inv1 = 1.0f/ls1;
    long long rowA = ((long long)bb*S_ + q0 + w*16 + lr)*D_ + hh*HD_;
    long long rowB = rowA + 8LL*D_;
    #pragma unroll
    for (int nf = 0; nf < 8; nf++) {
        int hd = nf*8 + lc;
        *(uint32_t*)(Ohi + rowA + hd) = pack2(Oacc[nf][0]*inv0, Oacc[nf][1]*inv0);
        *(uint32_t*)(Ohi + rowB + hd) = pack2(Oacc[nf][2]*inv1, Oacc[nf][3]*inv1);
    }
}

// ---------------------------- launch ---------------------------------------
extern "C" void kernel_launch(void* const* d_in, const int* in_sizes, int n_in,
                              void* d_out, int out_size)
{
    const float* x    = (const float*)d_in[0];
    const int*   adj  = (const int*)  d_in[1];
    const float* edge = (const float*)d_in[2];
    const float* ln1g = (const float*)d_in[3];
    const float* ln1b = (const float*)d_in[4];
    const float* ln2g = (const float*)d_in[5];
    const float* ln2b = (const float*)d_in[6];
    const float* wq = (const float*)d_in[7];  const float* bq = (const float*)d_in[8];
    const float* wk = (const float*)d_in[9];  const float* bk = (const float*)d_in[10];
    const float* wv = (const float*)d_in[11]; const float* bv = (const float*)d_in[12];
    const float* wo = (const float*)d_in[13]; const float* bo = (const float*)d_in[14];
    const float* w1 = (const float*)d_in[15]; const float* b1 = (const float*)d_in[16];
    const float* w2 = (const float*)d_in[17]; const float* b2 = (const float*)d_in[18];
    float* out = (float*)d_out;

    float *x1;
    __half *biasc;
    cudaGetSymbolAddress((void**)&x1,    g_x1);
    cudaGetSymbolAddress((void**)&biasc, g_bias);
    __half *pah, *qah, *qh, *kh, *vh;
    __half *wqkvh, *woh, *w1h, *w2h;
    cudaGetSymbolAddress((void**)&pah, g_pa_hi);
    cudaGetSymbolAddress((void**)&qah, g_qa_hi);
    cudaGetSymbolAddress((void**)&qh, g_qh);
    cudaGetSymbolAddress((void**)&kh, g_kh); cudaGetSymbolAddress((void**)&vh, g_vh);
    cudaGetSymbolAddress((void**)&wqkvh, g_wqkv_hi);
    cudaGetSymbolAddress((void**)&woh, g_wo_hi);
    cudaGetSymbolAddress((void**)&w1h, g_w1_hi);
    cudaGetSymbolAddress((void**)&w2h, g_w2_hi);

    cudaFuncSetAttribute((const void*)mma_gemm<EPI_QKV>,
        cudaFuncAttributeMaxDynamicSharedMemorySize, GEMM_SMEM);
    cudaFuncSetAttribute((const void*)mma_gemm<EPI_RESID>,
        cudaFuncAttributeMaxDynamicSharedMemorySize, GEMM_SMEM);
    cudaFuncSetAttribute((const void*)mma_gemm<EPI_GELU>,
        cudaFuncAttributeMaxDynamicSharedMemorySize, GEMM_SMEM);
    cudaFuncSetAttribute(attn_mma_kernel,
        cudaFuncAttributeMaxDynamicSharedMemorySize, ATT_SMEM);

    // side stream + events, created once (outside graph capture on first call)
    static cudaStream_t s1 = nullptr;
    static cudaEvent_t evFork = nullptr, evW3 = nullptr, evJoinB = nullptr, evJoinW = nullptr;
    if (!s1) {
        cudaStreamCreateWithFlags(&s1, cudaStreamNonBlocking);
        cudaEventCreateWithFlags(&evFork, cudaEventDisableTiming);
        cudaEventCreateWithFlags(&evW3, cudaEventDisableTiming);
        cudaEventCreateWithFlags(&evJoinB, cudaEventDisableTiming);
        cudaEventCreateWithFlags(&evJoinW, cudaEventDisableTiming);
    }

    // fork: side stream does qkv weight conversion, bias, then wo/w1/w2 convs
    cudaEventRecord(evFork, 0);
    cudaStreamWaitEvent(s1, evFork, 0);
    dim3 wb(256);
    wconvT3_kernel<<<dim3(16,16,3), wb, 0, s1>>>(wq, wk, wv, wqkvh);
    cudaEventRecord(evW3, s1);
    bias_kernel<<<(B_*S_*S_/4)/256, 256, 0, s1>>>(
        (const int4*)adj, (const float4*)edge, (uint2*)biasc);
    cudaEventRecord(evJoinB, s1);
    wconvT_kernel<<<dim3(16,16), wb, 0, s1>>>(wo, woh, D_, D_);
    wconvT_kernel<<<dim3(64,16), wb, 0, s1>>>(w1, w1h, D_, DFF);
    wconvT_kernel<<<dim3(16,64), wb, 0, s1>>>(w2, w2h, DFF, D_);
    cudaEventRecord(evJoinW, s1);

    // main: LN1 (overlaps wconvT3) -> QKV gemm
    ln_f16_kernel<<<MTOK, 256>>>(x, ln1g, ln1b, pah);
    cudaStreamWaitEvent(0, evW3, 0);
    mma_gemm<EPI_QKV><<<dim3(12, 32), 256, GEMM_SMEM>>>(
        pah, wqkvh, bq, bk, bv, nullptr, nullptr, nullptr,
        qh, kh, vh, MTOK, 3*D_, D_);

    // join bias, then attention (128-row Q tiles)
    cudaStreamWaitEvent(0, evJoinB, 0);
    attn_mma_kernel<<<dim3(S_/128, H_, B_), 256, ATT_SMEM>>>(
        qh, kh, vh, biasc, pah);

    // join weights, then O projection + residual -> x1 (fp32)
    cudaStreamWaitEvent(0, evJoinW, 0);
    mma_gemm<EPI_RESID><<<dim3(4, 32), 256, GEMM_SMEM>>>(
        pah, woh, bo, nullptr, nullptr, x, x1, nullptr,
        nullptr, nullptr, nullptr, MTOK, D_, D_);

    // LN2 -> fp16 hi
    ln_f16_kernel<<<MTOK, 256>>>(x1, ln2g, ln2b, pah);

    // MLP up + exact GELU -> fp16 hi
    mma_gemm<EPI_GELU><<<dim3(16, 32), 256, GEMM_SMEM>>>(
        pah, w1h, b1, nullptr, nullptr, nullptr, nullptr, qah,
        nullptr, nullptr, nullptr, MTOK, DFF, D_);

    // MLP down + residual -> out
    mma_gemm<EPI_RESID><<<dim3(4, 32), 256, GEMM_SMEM>>>(
        qah, w2h, b2, nullptr, nullptr, x1, out, nullptr,
        nullptr, nullptr, nullptr, MTOK, D_, DFF);
}